// round 11
// baseline (speedup 1.0000x reference)
#include <cuda_runtime.h>
#include <cstdint>
#include <math.h>

// ---------------- problem constants ----------------
#define NTOK 2048      // B*S
#define D    1024
#define H    4096
#define HE   4096
#define E    8
#define LN_EPS 1e-5f

// ---------------- scratch (device globals) ----------------
__device__ float g_h    [NTOK * D];
__device__ float g_xhat [NTOK * D];
__device__ float g_r    [NTOK * D];
__device__ float g_rh   [NTOK * H];
__device__ int   g_counts[E];
__device__ int   g_base  [E];
__device__ int   g_perm  [E * NTOK];
__device__ int   g_te   [NTOK * 2];
__device__ int   g_tp   [NTOK * 2];
__device__ float g_tg   [NTOK * 2];
__device__ float g_y    [2 * NTOK * D];
__device__ float g_f1   [2 * NTOK * HE];
__device__ float g_f2   [2 * NTOK * D];
__device__ float g_cln  [NTOK * D];
__device__ float g_ch   [NTOK * 2 * D];
__device__ float g_co   [NTOK * D];

// ---------------- helpers ----------------
__device__ __forceinline__ float gelu_f(float x) {
    return 0.5f * x * (1.0f + erff(x * 0.7071067811865475f));
}
__device__ __forceinline__ float to_tf32(float x) {
    uint32_t u;
    asm("cvt.rna.tf32.f32 %0, %1;" : "=r"(u) : "f"(x));
    return __uint_as_float(u);
}
__device__ __forceinline__ uint32_t smem_u32(const void* p) {
    uint32_t a;
    asm("{ .reg .u64 t; cvta.to.shared.u64 t, %1; cvt.u32.u64 %0, t; }" : "=r"(a) : "l"(p));
    return a;
}
__device__ __forceinline__ float warp_sum(float v) {
#pragma unroll
    for (int o = 16; o; o >>= 1) v += __shfl_xor_sync(0xffffffffu, v, o);
    return v;
}

// cp.async (baseline PTX, compute_80+)
#define CP_ASYNC_CG(dst, src, srcsz) \
    asm volatile("cp.async.cg.shared.global [%0], [%1], 16, %2;" \
        :: "r"(dst), "l"(src), "r"(srcsz) : "memory")
#define CP_COMMIT() asm volatile("cp.async.commit_group;" ::: "memory")
#define CP_WAIT2()  asm volatile("cp.async.wait_group 2;" ::: "memory")

__device__ __forceinline__ void mma_tf32(float* c, const uint32_t* a, const uint32_t* b) {
    asm volatile(
        "mma.sync.aligned.m16n8k8.row.col.f32.tf32.tf32.f32 "
        "{%0,%1,%2,%3}, {%4,%5,%6,%7}, {%8,%9}, {%0,%1,%2,%3};"
        : "+f"(c[0]), "+f"(c[1]), "+f"(c[2]), "+f"(c[3])
        : "r"(a[0]), "r"(a[1]), "r"(a[2]), "r"(a[3]), "r"(b[0]), "r"(b[1]));
}

// ---------------- elementwise (warp-per-token) ----------------
__global__ void zero_counts_kernel(int* counts) {
    if (threadIdx.x < E) counts[threadIdx.x] = 0;
}

// h = x + pos; LN(h) -> xhat (no affine); r = tf32(xhat*g+b)
__global__ void posln_kernel(const float* __restrict__ x,
                             const float* __restrict__ g, const float* __restrict__ b,
                             float* __restrict__ h, float* __restrict__ xhat,
                             float* __restrict__ r) {
    int wid = threadIdx.x >> 5, lane = threadIdx.x & 31;
    int t = blockIdx.x * 8 + wid;
    int sp = t & 1023;
    const float LOG1E4 = 9.210340371976184f;
    const float4* xr = (const float4*)(x + (size_t)t * D);
    float4 v[8];
    float s = 0.f;
#pragma unroll
    for (int j = 0; j < 8; j++) {
        int idx = j * 32 + lane;
        float4 val = xr[idx];
        int d0 = idx * 4;
        float a0 = (float)sp * expf(-LOG1E4 * (float)d0 * (1.f / (float)D));
        float a1 = (float)sp * expf(-LOG1E4 * (float)(d0 + 2) * (1.f / (float)D));
        float s0, c0, s1, c1;
        sincosf(a0, &s0, &c0);
        sincosf(a1, &s1, &c1);
        val.x += s0; val.y += c0;
        val.z += s1; val.w += c1;
        v[j] = val;
        s += val.x + val.y + val.z + val.w;
    }
    float mean = warp_sum(s) * (1.f / (float)D);
    float q = 0.f;
#pragma unroll
    for (int j = 0; j < 8; j++) {
        float dx = v[j].x - mean, dy = v[j].y - mean, dz = v[j].z - mean, dw = v[j].w - mean;
        q += dx * dx + dy * dy + dz * dz + dw * dw;
    }
    float rstd = rsqrtf(warp_sum(q) * (1.f / (float)D) + LN_EPS);
    float4* hr = (float4*)(h + (size_t)t * D);
    float4* xh = (float4*)(xhat + (size_t)t * D);
    float4* rr = (float4*)(r + (size_t)t * D);
    const float4* g4 = (const float4*)g;
    const float4* b4 = (const float4*)b;
#pragma unroll
    for (int j = 0; j < 8; j++) {
        int idx = j * 32 + lane;
        float4 val = v[j];
        hr[idx] = val;
        float4 xo;
        xo.x = (val.x - mean) * rstd; xo.y = (val.y - mean) * rstd;
        xo.z = (val.z - mean) * rstd; xo.w = (val.w - mean) * rstd;
        xh[idx] = xo;
        float4 gg = g4[idx], bb = b4[idx], ro;
        ro.x = to_tf32(xo.x * gg.x + bb.x); ro.y = to_tf32(xo.y * gg.y + bb.y);
        ro.z = to_tf32(xo.z * gg.z + bb.z); ro.w = to_tf32(xo.w * gg.w + bb.w);
        rr[idx] = ro;
    }
}

// out = LN(h + co) * g + b
__global__ void lnout_kernel(const float* __restrict__ X, const float* __restrict__ X2,
                             const float* __restrict__ g, const float* __restrict__ b,
                             float* __restrict__ out) {
    int wid = threadIdx.x >> 5, lane = threadIdx.x & 31;
    int t = blockIdx.x * 8 + wid;
    const float4* xr = (const float4*)(X + (size_t)t * D);
    const float4* x2 = (const float4*)(X2 + (size_t)t * D);
    float4 v[8];
    float s = 0.f;
#pragma unroll
    for (int j = 0; j < 8; j++) {
        int idx = j * 32 + lane;
        float4 a = xr[idx], c = x2[idx];
        a.x += c.x; a.y += c.y; a.z += c.z; a.w += c.w;
        v[j] = a;
        s += a.x + a.y + a.z + a.w;
    }
    float mean = warp_sum(s) * (1.f / (float)D);
    float q = 0.f;
#pragma unroll
    for (int j = 0; j < 8; j++) {
        float dx = v[j].x - mean, dy = v[j].y - mean, dz = v[j].z - mean, dw = v[j].w - mean;
        q += dx * dx + dy * dy + dz * dz + dw * dw;
    }
    float rstd = rsqrtf(warp_sum(q) * (1.f / (float)D) + LN_EPS);
    float4* o4 = (float4*)(out + (size_t)t * D);
    const float4* g4 = (const float4*)g;
    const float4* b4 = (const float4*)b;
#pragma unroll
    for (int j = 0; j < 8; j++) {
        int idx = j * 32 + lane;
        float4 gg = g4[idx], bb = b4[idx], o;
        o.x = (v[j].x - mean) * rstd * gg.x + bb.x;
        o.y = (v[j].y - mean) * rstd * gg.y + bb.y;
        o.z = (v[j].z - mean) * rstd * gg.z + bb.z;
        o.w = (v[j].w - mean) * rstd * gg.w + bb.w;
        o4[idx] = o;
    }
}

// combined = g1*f2[row1] + g2*f2[row2]; cln = tf32(LN(combined)*g+b)
__global__ void combine_ln_kernel(const float* __restrict__ f2, const int* __restrict__ bases,
                                  const int* __restrict__ te, const int* __restrict__ tp,
                                  const float* __restrict__ tg,
                                  const float* __restrict__ g, const float* __restrict__ b,
                                  float* __restrict__ cln) {
    int wid = threadIdx.x >> 5, lane = threadIdx.x & 31;
    int t = blockIdx.x * 8 + wid;
    int e1 = te[2 * t], e2 = te[2 * t + 1];
    int p1 = tp[2 * t], p2 = tp[2 * t + 1];
    float g1 = tg[2 * t], g2 = tg[2 * t + 1];
    const float4* r1 = (const float4*)(f2 + (size_t)(bases[e1] + p1) * D);
    const float4* r2 = (const float4*)(f2 + (size_t)(bases[e2] + p2) * D);
    float4 v[8];
    float s = 0.f;
#pragma unroll
    for (int j = 0; j < 8; j++) {
        int idx = j * 32 + lane;
        float4 a = r1[idx], c = r2[idx], o;
        o.x = g1 * a.x + g2 * c.x; o.y = g1 * a.y + g2 * c.y;
        o.z = g1 * a.z + g2 * c.z; o.w = g1 * a.w + g2 * c.w;
        v[j] = o;
        s += o.x + o.y + o.z + o.w;
    }
    float mean = warp_sum(s) * (1.f / (float)D);
    float q = 0.f;
#pragma unroll
    for (int j = 0; j < 8; j++) {
        float dx = v[j].x - mean, dy = v[j].y - mean, dz = v[j].z - mean, dw = v[j].w - mean;
        q += dx * dx + dy * dy + dz * dz + dw * dw;
    }
    float rstd = rsqrtf(warp_sum(q) * (1.f / (float)D) + LN_EPS);
    float4* o4 = (float4*)(cln + (size_t)t * D);
    const float4* g4 = (const float4*)g;
    const float4* b4 = (const float4*)b;
#pragma unroll
    for (int j = 0; j < 8; j++) {
        int idx = j * 32 + lane;
        float4 gg = g4[idx], bb = b4[idx], o;
        o.x = to_tf32((v[j].x - mean) * rstd * gg.x + bb.x);
        o.y = to_tf32((v[j].y - mean) * rstd * gg.y + bb.y);
        o.z = to_tf32((v[j].z - mean) * rstd * gg.z + bb.z);
        o.w = to_tf32((v[j].w - mean) * rstd * gg.w + bb.w);
        o4[idx] = o;
    }
}

// gather: y[base[e]+i] = tf32(xhat[perm]*eg+eb)
__global__ void gather_kernel(const float* __restrict__ xhat, const float* __restrict__ elng,
                              const float* __restrict__ elnb, const int* __restrict__ counts,
                              const int* __restrict__ bases, const int* __restrict__ perm,
                              float* __restrict__ y) {
    int wid = threadIdx.x >> 5, lane = threadIdx.x & 31;
    int e = blockIdx.y;
    int i = blockIdx.x * 8 + wid;
    if (i >= counts[e]) return;
    int t = perm[e * NTOK + i];
    const float4* src = (const float4*)(xhat + (size_t)t * D);
    const float4* g4 = (const float4*)(elng + (size_t)e * D);
    const float4* b4 = (const float4*)(elnb + (size_t)e * D);
    float4* dst = (float4*)(y + (size_t)(bases[e] + i) * D);
#pragma unroll
    for (int j = 0; j < 8; j++) {
        int idx = j * 32 + lane;
        float4 s = src[idx], gg = g4[idx], bb = b4[idx], o;
        o.x = to_tf32(s.x * gg.x + bb.x); o.y = to_tf32(s.y * gg.y + bb.y);
        o.z = to_tf32(s.z * gg.z + bb.z); o.w = to_tf32(s.w * gg.w + bb.w);
        dst[idx] = o;
    }
}

// router: TWO warps per token (each handles H/2), smem combine, top2 by lane 0
__global__ void router_kernel(const float* __restrict__ rh, const float* __restrict__ w2,
                              const float* __restrict__ b2, const float* __restrict__ temp,
                              int* __restrict__ counts, int* __restrict__ perm,
                              int* __restrict__ te, int* __restrict__ tp,
                              float* __restrict__ tg) {
    __shared__ float part[4][2][E];
    int wid = threadIdx.x >> 5, lane = threadIdx.x & 31;
    int tl = wid >> 1, half = wid & 1;
    int t = blockIdx.x * 4 + tl;
    const float* row = rh + (size_t)t * H + half * (H / 2);
    const float4* w4 = (const float4*)(w2 + (size_t)(half * (H / 2)) * E);
    float acc[E];
#pragma unroll
    for (int e = 0; e < E; e++) acc[e] = 0.f;
#pragma unroll 8
    for (int j = 0; j < (H / 2) / 32; j++) {
        int k = j * 32 + lane;
        float v = row[k];
        float4 w0 = w4[k * 2];
        float4 w1 = w4[k * 2 + 1];
        acc[0] += v * w0.x; acc[1] += v * w0.y; acc[2] += v * w0.z; acc[3] += v * w0.w;
        acc[4] += v * w1.x; acc[5] += v * w1.y; acc[6] += v * w1.z; acc[7] += v * w1.w;
    }
#pragma unroll
    for (int e = 0; e < E; e++) acc[e] = warp_sum(acc[e]);
    if (lane == 0) {
#pragma unroll
        for (int e = 0; e < E; e++) part[tl][half][e] = acc[e];
    }
    __syncthreads();
    if (half == 0 && lane == 0) {
        float invt = 1.0f / temp[0];
        float p[E];
        float mx = -1e30f;
#pragma unroll
        for (int e = 0; e < E; e++) {
            p[e] = (part[tl][0][e] + part[tl][1][e] + b2[e]) * invt;
            mx = fmaxf(mx, p[e]);
        }
        float se = 0.f;
#pragma unroll
        for (int e = 0; e < E; e++) { p[e] = expf(p[e] - mx); se += p[e]; }
        float inv = 1.0f / se;
#pragma unroll
        for (int e = 0; e < E; e++) p[e] *= inv;
        int i1 = 0;
#pragma unroll
        for (int e = 1; e < E; e++) if (p[e] > p[i1]) i1 = e;
        int i2 = (i1 == 0) ? 1 : 0;
#pragma unroll
        for (int e = 0; e < E; e++) if (e != i1 && p[e] > p[i2]) i2 = e;
        int pos1 = atomicAdd(&counts[i1], 1);
        perm[i1 * NTOK + pos1] = t;
        int pos2 = atomicAdd(&counts[i2], 1);
        perm[i2 * NTOK + pos2] = t;
        te[2 * t] = i1; tp[2 * t] = pos1; tg[2 * t] = p[i1];
        te[2 * t + 1] = i2; tp[2 * t + 1] = pos2; tg[2 * t + 1] = p[i2];
    }
}

__global__ void base_kernel(const int* __restrict__ counts, int* __restrict__ bases) {
    int s = 0;
    for (int e = 0; e < E; e++) { bases[e] = s; s += counts[e]; }
}

// ---------------- tf32 mma.sync GEMM (software-pipelined fragments) ----------
// C[M,N] = act(A[M,K] @ B[K,N] + bias[N]); A K-contig, B N-contig.
// BM in {128,64}, BN=128, BK=16, 128 threads (4 warps), FIVE-stage cp.async.
// Issue-first ordering; 5 stages make the overwrite provably barrier-separated.
// k-slot remap: MMA k-slot q holds original k=2q, slot q+4 holds k=2q+1 (A and
// B agree, so the dot product is identical). This makes each thread's A pair
// (a0,a2)/(a1,a3) ADJACENT floats -> LDS.64, halving A fragment-load issues.
#define NSTG 5

template <int BM, int WN, bool DOGELU, bool ROUND, bool GROUPED>
__global__ void __launch_bounds__(128, (BM == 128) ? 2 : 3)
mma_gemm(const float* __restrict__ Abase, const float* __restrict__ Ball,
         const float* __restrict__ biasall, float* __restrict__ Cbase,
         const int* __restrict__ counts, const int* __restrict__ bases,
         int M_in, int N, int K) {
    constexpr int NT = WN / 8;
    constexpr int ACH = BM / 32;
    constexpr int ASTF = BM * 20;
    constexpr int STGF = ASTF + 16 * 136;
    constexpr int STGB = STGF * 4;

    int e = GROUPED ? blockIdx.z : 0;
    int M = GROUPED ? counts[e] : M_in;
    int m0 = blockIdx.y * BM;
    if (m0 >= M) return;
    int n0 = blockIdx.x * 128;
    const float* A = GROUPED ? Abase + (size_t)bases[e] * K : Abase;
    const float* B = GROUPED ? Ball + (size_t)e * (size_t)K * N : Ball;
    const float* bias = GROUPED ? biasall + (size_t)e * N : biasall;
    float* C = GROUPED ? Cbase + (size_t)bases[e] * N : Cbase;

    extern __shared__ float smf[];
    uint32_t sbase = smem_u32(smf);
    int tid = threadIdx.x;
    int wid = tid >> 5, lane = tid & 31;
    int gq = lane >> 2, qq = lane & 3;
    int m0w = (BM == 128) ? (wid & 1) * 64 : 0;
    int n0w = (BM == 128) ? (wid >> 1) * 64 : wid * 32;

    int aq = tid & 3, ar = tid >> 2;
    int bq = tid & 31, br = tid >> 5;
    uint32_t adst[ACH], bdst[4];
    const float* asrc[ACH];
    const float* bsrc[4];
    uint32_t asz[ACH];
#pragma unroll
    for (int i = 0; i < ACH; i++) {
        int r = ar + 32 * i;
        adst[i] = (uint32_t)(r * 80 + aq * 16);
        int row = m0 + r;
        asz[i] = (row < M) ? 16u : 0u;
        asrc[i] = A + (size_t)((row < M) ? row : 0) * K + aq * 4;
    }
#pragma unroll
    for (int i = 0; i < 4; i++) {
        int rb = br + 4 * i;
        bdst[i] = (uint32_t)(ASTF * 4 + rb * 544 + bq * 16);
        bsrc[i] = B + (size_t)rb * N + n0 + bq * 4;
    }

    const int NC = K / 16;

    float acc[4][NT][4];
#pragma unroll
    for (int i = 0; i < 4; i++)
#pragma unroll
        for (int j = 0; j < NT; j++)
#pragma unroll
            for (int l = 0; l < 4; l++) acc[i][j][l] = 0.f;

    // prologue: stages 0,1,2
#pragma unroll
    for (int pk = 0; pk < 3; pk++) {
        uint32_t sb = sbase + pk * STGB;
        int k0 = pk * 16;
#pragma unroll
        for (int i = 0; i < ACH; i++) CP_ASYNC_CG(sb + adst[i], asrc[i] + k0, asz[i]);
#pragma unroll
        for (int i = 0; i < 4; i++) CP_ASYNC_CG(sb + bdst[i], bsrc[i] + (size_t)k0 * N, 16u);
        CP_COMMIT();
    }
    CP_WAIT2();            // stage 0 resident
    __syncthreads();

    // fragment double buffers
    uint32_t a0[4][4], b0[NT][2], a1[4][4], b1[NT][2];

#define LOADFRAG(AF, BF, ASP, BSP, KK)                                        \
    do {                                                                      \
        _Pragma("unroll")                                                     \
        for (int mt = 0; mt < 4; mt++) {                                      \
            int r = m0w + mt * 16 + gq;                                       \
            float2 av0 = *(const float2*)&(ASP)[r * 20 + (KK) + 2 * qq];      \
            float2 av1 = *(const float2*)&(ASP)[(r + 8) * 20 + (KK) + 2 * qq];\
            AF[mt][0] = __float_as_uint(av0.x);                               \
            AF[mt][1] = __float_as_uint(av1.x);                               \
            AF[mt][2] = __float_as_uint(av0.y);                               \
            AF[mt][3] = __float_as_uint(av1.y);                               \
        }                                                                     \
        _Pragma("unroll")                                                     \
        for (int nt = 0; nt < NT; nt++) {                                     \
            int c = n0w + nt * 8 + gq;                                        \
            BF[nt][0] = __float_as_uint((BSP)[((KK) + 2 * qq) * 136 + c]);    \
            BF[nt][1] = __float_as_uint((BSP)[((KK) + 2 * qq + 1) * 136 + c]);\
        }                                                                     \
    } while (0)

#define MMAALL(AF, BF)                                                        \
    do {                                                                      \
        _Pragma("unroll")                                                     \
        for (int mt = 0; mt < 4; mt++)                                        \
            _Pragma("unroll")                                                 \
            for (int nt = 0; nt < NT; nt++)                                   \
                mma_tf32(acc[mt][nt], AF[mt], BF[nt]);                        \
    } while (0)

    {
        const float* As0 = smf;
        const float* Bs0 = smf + ASTF;
        LOADFRAG(a0, b0, As0, Bs0, 0);
    }

    int sc = 0;   // slot of stage kc
    for (int kc = 0; kc < NC; kc++) {
        // issue stage kc+3 into slot (sc+3)%5 (held stage kc-2; reads finished
        // at iter kc-2, separated from this write by barrier at iter kc-1)
        if (kc + 3 < NC) {
            int si = sc + 3; if (si >= NSTG) si -= NSTG;
            uint32_t sb = sbase + si * STGB;
            int k0 = (kc + 3) * 16;
#pragma unroll
            for (int i = 0; i < ACH; i++) CP_ASYNC_CG(sb + adst[i], asrc[i] + k0, asz[i]);
#pragma unroll
            for (int i = 0; i < 4; i++) CP_ASYNC_CG(sb + bdst[i], bsrc[i] + (size_t)k0 * N, 16u);
        }
        CP_COMMIT();
        CP_WAIT2();        // groups <= kc+1 complete -> stages kc, kc+1 resident
        __syncthreads();

        const float* Asc = smf + sc * STGF;
        const float* Bsc = Asc + ASTF;
        int sn = (kc + 1 < NC) ? ((sc + 1 == NSTG) ? 0 : sc + 1) : sc;
        const float* Asn = smf + sn * STGF;
        const float* Bsn = Asn + ASTF;

        LOADFRAG(a1, b1, Asc, Bsc, 8);   // prefetch k8=1 of this stage
        MMAALL(a0, b0);                  // compute k8=0
        LOADFRAG(a0, b0, Asn, Bsn, 0);   // prefetch k8=0 of next stage
        MMAALL(a1, b1);                  // compute k8=1

        sc = (sc + 1 == NSTG) ? 0 : sc + 1;
    }
#undef LOADFRAG
#undef MMAALL

    // epilogue
#pragma unroll
    for (int mt = 0; mt < 4; mt++) {
        int row0 = m0 + m0w + mt * 16 + gq;
        int row1 = row0 + 8;
#pragma unroll
        for (int nt = 0; nt < NT; nt++) {
            int col = n0 + n0w + nt * 8 + 2 * qq;
            float bb0 = bias[col], bb1 = bias[col + 1];
            float v0 = acc[mt][nt][0] + bb0;
            float v1 = acc[mt][nt][1] + bb1;
            float v2 = acc[mt][nt][2] + bb0;
            float v3 = acc[mt][nt][3] + bb1;
            if (DOGELU) { v0 = gelu_f(v0); v1 = gelu_f(v1); v2 = gelu_f(v2); v3 = gelu_f(v3); }
            if (ROUND)  { v0 = to_tf32(v0); v1 = to_tf32(v1); v2 = to_tf32(v2); v3 = to_tf32(v3); }
            if (row0 < M) *(float2*)(C + (size_t)row0 * N + col) = make_float2(v0, v1);
            if (row1 < M) *(float2*)(C + (size_t)row1 * N + col) = make_float2(v2, v3);
        }
    }
}

#define SMEM_BIG   (NSTG * (128 * 20 + 16 * 136) * 4)
#define SMEM_SMALL (NSTG * (64 * 20 + 16 * 136) * 4)

// ---------------- launch ----------------
extern "C" void kernel_launch(void* const* d_in, const int* in_sizes, int n_in,
                              void* d_out, int out_size) {
    const float* x      = (const float*)d_in[0];
    const float* r_ln_g = (const float*)d_in[1];
    const float* r_ln_b = (const float*)d_in[2];
    const float* r_w1   = (const float*)d_in[3];
    const float* r_b1   = (const float*)d_in[4];
    const float* r_w2   = (const float*)d_in[5];
    const float* r_b2   = (const float*)d_in[6];
    const float* temp   = (const float*)d_in[7];
    const float* e_ln_g = (const float*)d_in[8];
    const float* e_ln_b = (const float*)d_in[9];
    const float* e_w1   = (const float*)d_in[10];
    const float* e_b1   = (const float*)d_in[11];
    const float* e_w2   = (const float*)d_in[12];
    const float* e_b2   = (const float*)d_in[13];
    const float* c_ln_g = (const float*)d_in[14];
    const float* c_ln_b = (const float*)d_in[15];
    const float* c_w1   = (const float*)d_in[16];
    const float* c_b1   = (const float*)d_in[17];
    const float* c_w2   = (const float*)d_in[18];
    const float* c_b2   = (const float*)d_in[19];
    const float* o_ln_g = (const float*)d_in[20];
    const float* o_ln_b = (const float*)d_in[21];
    float* out = (float*)d_out;

    float *p_h, *p_xhat, *p_r, *p_rh, *p_tg, *p_y, *p_f1, *p_f2, *p_cln, *p_ch, *p_co;
    int *p_counts, *p_base, *p_perm, *p_te, *p_tp;
    cudaGetSymbolAddress((void**)&p_h, g_h);
    cudaGetSymbolAddress((void**)&p_xhat, g_xhat);
    cudaGetSymbolAddress((void**)&p_r, g_r);
    cudaGetSymbolAddress((void**)&p_rh, g_rh);
    cudaGetSymbolAddress((void**)&p_counts, g_counts);
    cudaGetSymbolAddress((void**)&p_base, g_base);
    cudaGetSymbolAddress((void**)&p_perm, g_perm);
    cudaGetSymbolAddress((void**)&p_te, g_te);
    cudaGetSymbolAddress((void**)&p_tp, g_tp);
    cudaGetSymbolAddress((void**)&p_tg, g_tg);
    cudaGetSymbolAddress((void**)&p_y, g_y);
    cudaGetSymbolAddress((void**)&p_f1, g_f1);
    cudaGetSymbolAddress((void**)&p_f2, g_f2);
    cudaGetSymbolAddress((void**)&p_cln, g_cln);
    cudaGetSymbolAddress((void**)&p_ch, g_ch);
    cudaGetSymbolAddress((void**)&p_co, g_co);

    cudaFuncSetAttribute(mma_gemm<128, 64, true,  false, false>, cudaFuncAttributeMaxDynamicSharedMemorySize, SMEM_BIG);
    cudaFuncSetAttribute(mma_gemm<128, 64, true,  true,  true >, cudaFuncAttributeMaxDynamicSharedMemorySize, SMEM_BIG);
    cudaFuncSetAttribute(mma_gemm<128, 64, false, false, true >, cudaFuncAttributeMaxDynamicSharedMemorySize, SMEM_BIG);
    cudaFuncSetAttribute(mma_gemm<128, 64, true,  true,  false>, cudaFuncAttributeMaxDynamicSharedMemorySize, SMEM_BIG);
    cudaFuncSetAttribute(mma_gemm<64,  32, false, false, false>, cudaFuncAttributeMaxDynamicSharedMemorySize, SMEM_SMALL);

    // 0. zero expert counts
    zero_counts_kernel<<<1, 32>>>(p_counts);
    // 1+2. h = x + pos; shared LN -> xhat; router input r (tf32)
    posln_kernel<<<NTOK / 8, 256>>>(x, r_ln_g, r_ln_b, p_h, p_xhat, p_r);
    // 3. router hidden: rh = gelu(r @ r_w1 + r_b1)
    mma_gemm<128, 64, true, false, false><<<dim3(H / 128, NTOK / 128), 128, SMEM_BIG>>>(
        p_r, r_w1, r_b1, p_rh, nullptr, nullptr, NTOK, H, D);
    // 4. router logits -> top2 -> compaction (2 warps/token)
    router_kernel<<<NTOK / 4, 256>>>(p_rh, r_w2, r_b2, temp, p_counts, p_perm, p_te, p_tp, p_tg);
    // 5. prefix sums
    base_kernel<<<1, 1>>>(p_counts, p_base);
    // 6. gather expert inputs (per-expert LN affine, tf32)
    gather_kernel<<<dim3(NTOK / 8, E), 256>>>(p_xhat, e_ln_g, e_ln_b, p_counts, p_base, p_perm, p_y);
    // 7. expert FFN layer 1
    mma_gemm<128, 64, true, true, true><<<dim3(HE / 128, NTOK / 128, E), 128, SMEM_BIG>>>(
        p_y, e_w1, e_b1, p_f1, p_counts, p_base, 0, HE, D);
    // 8. expert FFN layer 2
    mma_gemm<128, 64, false, false, true><<<dim3(D / 128, NTOK / 128, E), 128, SMEM_BIG>>>(
        p_f1, e_w2, e_b2, p_f2, p_counts, p_base, 0, D, HE);
    // 9+10. combine (gates) + combiner LN fused
    combine_ln_kernel<<<NTOK / 8, 256>>>(p_f2, p_base, p_te, p_tp, p_tg, c_ln_g, c_ln_b, p_cln);
    // 11. combiner MLP (gemm2 uses BM=64 variant: 256 CTAs, balanced waves)
    mma_gemm<128, 64, true, true, false><<<dim3(2 * D / 128, NTOK / 128), 128, SMEM_BIG>>>(
        p_cln, c_w1, c_b1, p_ch, nullptr, nullptr, NTOK, 2 * D, D);
    mma_gemm<64, 32, false, false, false><<<dim3(D / 128, NTOK / 64), 128, SMEM_SMALL>>>(
        p_ch, c_w2, c_b2, p_co, nullptr, nullptr, NTOK, D, 2 * D);
    // 12. out = LN(h + co)
    lnout_kernel<<<NTOK / 8, 256>>>(p_h, p_co, o_ln_g, o_ln_b, out);
}

// round 12
// speedup vs baseline: 1.1753x; 1.1753x over previous
#include <cuda_runtime.h>
#include <cstdint>
#include <math.h>

// ---------------- problem constants ----------------
#define NTOK 2048      // B*S
#define D    1024
#define H    4096
#define HE   4096
#define E    8
#define LN_EPS 1e-5f

// ---------------- scratch (device globals) ----------------
__device__ float g_h    [NTOK * D];
__device__ float g_xhat [NTOK * D];
__device__ float g_r    [NTOK * D];
__device__ float g_rh   [NTOK * H];
__device__ int   g_counts[E];
__device__ int   g_base  [E];
__device__ int   g_perm  [E * NTOK];
__device__ int   g_te   [NTOK * 2];
__device__ int   g_tp   [NTOK * 2];
__device__ float g_tg   [NTOK * 2];
__device__ float g_y    [2 * NTOK * D];
__device__ float g_f1   [2 * NTOK * HE];
__device__ float g_f2   [2 * NTOK * D];
__device__ float g_cln  [NTOK * D];
__device__ float g_ch   [NTOK * 2 * D];
__device__ float g_co   [NTOK * D];

// ---------------- helpers ----------------
__device__ __forceinline__ float gelu_f(float x) {
    return 0.5f * x * (1.0f + erff(x * 0.7071067811865475f));
}
__device__ __forceinline__ float to_tf32(float x) {
    uint32_t u;
    asm("cvt.rna.tf32.f32 %0, %1;" : "=r"(u) : "f"(x));
    return __uint_as_float(u);
}
__device__ __forceinline__ uint32_t smem_u32(const void* p) {
    uint32_t a;
    asm("{ .reg .u64 t; cvta.to.shared.u64 t, %1; cvt.u32.u64 %0, t; }" : "=r"(a) : "l"(p));
    return a;
}
__device__ __forceinline__ float warp_sum(float v) {
#pragma unroll
    for (int o = 16; o; o >>= 1) v += __shfl_xor_sync(0xffffffffu, v, o);
    return v;
}

// cp.async (baseline PTX, compute_80+)
#define CP_ASYNC_CG(dst, src, srcsz) \
    asm volatile("cp.async.cg.shared.global [%0], [%1], 16, %2;" \
        :: "r"(dst), "l"(src), "r"(srcsz) : "memory")
#define CP_COMMIT() asm volatile("cp.async.commit_group;" ::: "memory")
#define CP_WAIT2()  asm volatile("cp.async.wait_group 2;" ::: "memory")

__device__ __forceinline__ void mma_tf32(float* c, const uint32_t* a, const uint32_t* b) {
    asm volatile(
        "mma.sync.aligned.m16n8k8.row.col.f32.tf32.tf32.f32 "
        "{%0,%1,%2,%3}, {%4,%5,%6,%7}, {%8,%9}, {%0,%1,%2,%3};"
        : "+f"(c[0]), "+f"(c[1]), "+f"(c[2]), "+f"(c[3])
        : "r"(a[0]), "r"(a[1]), "r"(a[2]), "r"(a[3]), "r"(b[0]), "r"(b[1]));
}

// ---------------- elementwise (warp-per-token) ----------------
__global__ void zero_counts_kernel(int* counts) {
    if (threadIdx.x < E) counts[threadIdx.x] = 0;
}

// h = x + pos; LN(h) -> xhat (no affine); r = tf32(xhat*g+b)
__global__ void posln_kernel(const float* __restrict__ x,
                             const float* __restrict__ g, const float* __restrict__ b,
                             float* __restrict__ h, float* __restrict__ xhat,
                             float* __restrict__ r) {
    int wid = threadIdx.x >> 5, lane = threadIdx.x & 31;
    int t = blockIdx.x * 8 + wid;
    int sp = t & 1023;
    const float LOG1E4 = 9.210340371976184f;
    const float4* xr = (const float4*)(x + (size_t)t * D);
    float4 v[8];
    float s = 0.f;
#pragma unroll
    for (int j = 0; j < 8; j++) {
        int idx = j * 32 + lane;
        float4 val = xr[idx];
        int d0 = idx * 4;
        float a0 = (float)sp * expf(-LOG1E4 * (float)d0 * (1.f / (float)D));
        float a1 = (float)sp * expf(-LOG1E4 * (float)(d0 + 2) * (1.f / (float)D));
        float s0, c0, s1, c1;
        sincosf(a0, &s0, &c0);
        sincosf(a1, &s1, &c1);
        val.x += s0; val.y += c0;
        val.z += s1; val.w += c1;
        v[j] = val;
        s += val.x + val.y + val.z + val.w;
    }
    float mean = warp_sum(s) * (1.f / (float)D);
    float q = 0.f;
#pragma unroll
    for (int j = 0; j < 8; j++) {
        float dx = v[j].x - mean, dy = v[j].y - mean, dz = v[j].z - mean, dw = v[j].w - mean;
        q += dx * dx + dy * dy + dz * dz + dw * dw;
    }
    float rstd = rsqrtf(warp_sum(q) * (1.f / (float)D) + LN_EPS);
    float4* hr = (float4*)(h + (size_t)t * D);
    float4* xh = (float4*)(xhat + (size_t)t * D);
    float4* rr = (float4*)(r + (size_t)t * D);
    const float4* g4 = (const float4*)g;
    const float4* b4 = (const float4*)b;
#pragma unroll
    for (int j = 0; j < 8; j++) {
        int idx = j * 32 + lane;
        float4 val = v[j];
        hr[idx] = val;
        float4 xo;
        xo.x = (val.x - mean) * rstd; xo.y = (val.y - mean) * rstd;
        xo.z = (val.z - mean) * rstd; xo.w = (val.w - mean) * rstd;
        xh[idx] = xo;
        float4 gg = g4[idx], bb = b4[idx], ro;
        ro.x = to_tf32(xo.x * gg.x + bb.x); ro.y = to_tf32(xo.y * gg.y + bb.y);
        ro.z = to_tf32(xo.z * gg.z + bb.z); ro.w = to_tf32(xo.w * gg.w + bb.w);
        rr[idx] = ro;
    }
}

// out = LN(h + co) * g + b
__global__ void lnout_kernel(const float* __restrict__ X, const float* __restrict__ X2,
                             const float* __restrict__ g, const float* __restrict__ b,
                             float* __restrict__ out) {
    int wid = threadIdx.x >> 5, lane = threadIdx.x & 31;
    int t = blockIdx.x * 8 + wid;
    const float4* xr = (const float4*)(X + (size_t)t * D);
    const float4* x2 = (const float4*)(X2 + (size_t)t * D);
    float4 v[8];
    float s = 0.f;
#pragma unroll
    for (int j = 0; j < 8; j++) {
        int idx = j * 32 + lane;
        float4 a = xr[idx], c = x2[idx];
        a.x += c.x; a.y += c.y; a.z += c.z; a.w += c.w;
        v[j] = a;
        s += a.x + a.y + a.z + a.w;
    }
    float mean = warp_sum(s) * (1.f / (float)D);
    float q = 0.f;
#pragma unroll
    for (int j = 0; j < 8; j++) {
        float dx = v[j].x - mean, dy = v[j].y - mean, dz = v[j].z - mean, dw = v[j].w - mean;
        q += dx * dx + dy * dy + dz * dz + dw * dw;
    }
    float rstd = rsqrtf(warp_sum(q) * (1.f / (float)D) + LN_EPS);
    float4* o4 = (float4*)(out + (size_t)t * D);
    const float4* g4 = (const float4*)g;
    const float4* b4 = (const float4*)b;
#pragma unroll
    for (int j = 0; j < 8; j++) {
        int idx = j * 32 + lane;
        float4 gg = g4[idx], bb = b4[idx], o;
        o.x = (v[j].x - mean) * rstd * gg.x + bb.x;
        o.y = (v[j].y - mean) * rstd * gg.y + bb.y;
        o.z = (v[j].z - mean) * rstd * gg.z + bb.z;
        o.w = (v[j].w - mean) * rstd * gg.w + bb.w;
        o4[idx] = o;
    }
}

// combined = g1*f2[row1] + g2*f2[row2]; cln = tf32(LN(combined)*g+b)
__global__ void combine_ln_kernel(const float* __restrict__ f2, const int* __restrict__ bases,
                                  const int* __restrict__ te, const int* __restrict__ tp,
                                  const float* __restrict__ tg,
                                  const float* __restrict__ g, const float* __restrict__ b,
                                  float* __restrict__ cln) {
    int wid = threadIdx.x >> 5, lane = threadIdx.x & 31;
    int t = blockIdx.x * 8 + wid;
    int e1 = te[2 * t], e2 = te[2 * t + 1];
    int p1 = tp[2 * t], p2 = tp[2 * t + 1];
    float g1 = tg[2 * t], g2 = tg[2 * t + 1];
    const float4* r1 = (const float4*)(f2 + (size_t)(bases[e1] + p1) * D);
    const float4* r2 = (const float4*)(f2 + (size_t)(bases[e2] + p2) * D);
    float4 v[8];
    float s = 0.f;
#pragma unroll
    for (int j = 0; j < 8; j++) {
        int idx = j * 32 + lane;
        float4 a = r1[idx], c = r2[idx], o;
        o.x = g1 * a.x + g2 * c.x; o.y = g1 * a.y + g2 * c.y;
        o.z = g1 * a.z + g2 * c.z; o.w = g1 * a.w + g2 * c.w;
        v[j] = o;
        s += o.x + o.y + o.z + o.w;
    }
    float mean = warp_sum(s) * (1.f / (float)D);
    float q = 0.f;
#pragma unroll
    for (int j = 0; j < 8; j++) {
        float dx = v[j].x - mean, dy = v[j].y - mean, dz = v[j].z - mean, dw = v[j].w - mean;
        q += dx * dx + dy * dy + dz * dz + dw * dw;
    }
    float rstd = rsqrtf(warp_sum(q) * (1.f / (float)D) + LN_EPS);
    float4* o4 = (float4*)(cln + (size_t)t * D);
    const float4* g4 = (const float4*)g;
    const float4* b4 = (const float4*)b;
#pragma unroll
    for (int j = 0; j < 8; j++) {
        int idx = j * 32 + lane;
        float4 gg = g4[idx], bb = b4[idx], o;
        o.x = to_tf32((v[j].x - mean) * rstd * gg.x + bb.x);
        o.y = to_tf32((v[j].y - mean) * rstd * gg.y + bb.y);
        o.z = to_tf32((v[j].z - mean) * rstd * gg.z + bb.z);
        o.w = to_tf32((v[j].w - mean) * rstd * gg.w + bb.w);
        o4[idx] = o;
    }
}

// gather: y[base[e]+i] = tf32(xhat[perm]*eg+eb)
__global__ void gather_kernel(const float* __restrict__ xhat, const float* __restrict__ elng,
                              const float* __restrict__ elnb, const int* __restrict__ counts,
                              const int* __restrict__ bases, const int* __restrict__ perm,
                              float* __restrict__ y) {
    int wid = threadIdx.x >> 5, lane = threadIdx.x & 31;
    int e = blockIdx.y;
    int i = blockIdx.x * 8 + wid;
    if (i >= counts[e]) return;
    int t = perm[e * NTOK + i];
    const float4* src = (const float4*)(xhat + (size_t)t * D);
    const float4* g4 = (const float4*)(elng + (size_t)e * D);
    const float4* b4 = (const float4*)(elnb + (size_t)e * D);
    float4* dst = (float4*)(y + (size_t)(bases[e] + i) * D);
#pragma unroll
    for (int j = 0; j < 8; j++) {
        int idx = j * 32 + lane;
        float4 s = src[idx], gg = g4[idx], bb = b4[idx], o;
        o.x = to_tf32(s.x * gg.x + bb.x); o.y = to_tf32(s.y * gg.y + bb.y);
        o.z = to_tf32(s.z * gg.z + bb.z); o.w = to_tf32(s.w * gg.w + bb.w);
        dst[idx] = o;
    }
}

// router: TWO warps per token (each handles H/2), smem combine, top2 by lane 0
__global__ void router_kernel(const float* __restrict__ rh, const float* __restrict__ w2,
                              const float* __restrict__ b2, const float* __restrict__ temp,
                              int* __restrict__ counts, int* __restrict__ perm,
                              int* __restrict__ te, int* __restrict__ tp,
                              float* __restrict__ tg) {
    __shared__ float part[4][2][E];
    int wid = threadIdx.x >> 5, lane = threadIdx.x & 31;
    int tl = wid >> 1, half = wid & 1;
    int t = blockIdx.x * 4 + tl;
    const float* row = rh + (size_t)t * H + half * (H / 2);
    const float4* w4 = (const float4*)(w2 + (size_t)(half * (H / 2)) * E);
    float acc[E];
#pragma unroll
    for (int e = 0; e < E; e++) acc[e] = 0.f;
#pragma unroll 8
    for (int j = 0; j < (H / 2) / 32; j++) {
        int k = j * 32 + lane;
        float v = row[k];
        float4 w0 = w4[k * 2];
        float4 w1 = w4[k * 2 + 1];
        acc[0] += v * w0.x; acc[1] += v * w0.y; acc[2] += v * w0.z; acc[3] += v * w0.w;
        acc[4] += v * w1.x; acc[5] += v * w1.y; acc[6] += v * w1.z; acc[7] += v * w1.w;
    }
#pragma unroll
    for (int e = 0; e < E; e++) acc[e] = warp_sum(acc[e]);
    if (lane == 0) {
#pragma unroll
        for (int e = 0; e < E; e++) part[tl][half][e] = acc[e];
    }
    __syncthreads();
    if (half == 0 && lane == 0) {
        float invt = 1.0f / temp[0];
        float p[E];
        float mx = -1e30f;
#pragma unroll
        for (int e = 0; e < E; e++) {
            p[e] = (part[tl][0][e] + part[tl][1][e] + b2[e]) * invt;
            mx = fmaxf(mx, p[e]);
        }
        float se = 0.f;
#pragma unroll
        for (int e = 0; e < E; e++) { p[e] = expf(p[e] - mx); se += p[e]; }
        float inv = 1.0f / se;
#pragma unroll
        for (int e = 0; e < E; e++) p[e] *= inv;
        int i1 = 0;
#pragma unroll
        for (int e = 1; e < E; e++) if (p[e] > p[i1]) i1 = e;
        int i2 = (i1 == 0) ? 1 : 0;
#pragma unroll
        for (int e = 0; e < E; e++) if (e != i1 && p[e] > p[i2]) i2 = e;
        int pos1 = atomicAdd(&counts[i1], 1);
        perm[i1 * NTOK + pos1] = t;
        int pos2 = atomicAdd(&counts[i2], 1);
        perm[i2 * NTOK + pos2] = t;
        te[2 * t] = i1; tp[2 * t] = pos1; tg[2 * t] = p[i1];
        te[2 * t + 1] = i2; tp[2 * t + 1] = pos2; tg[2 * t + 1] = p[i2];
    }
}

__global__ void base_kernel(const int* __restrict__ counts, int* __restrict__ bases) {
    int s = 0;
    for (int e = 0; e < E; e++) { bases[e] = s; s += counts[e]; }
}

// ---------------- tf32 mma.sync GEMM (software-pipelined fragments) ----------
// C[M,N] = act(A[M,K] @ B[K,N] + bias[N]); A K-contig, B N-contig.
// BM in {128,64}, BN=128, BK=16, 128 threads (4 warps), FIVE-stage cp.async.
// k-slot remap (slot q <-> k=2q, slot q+4 <-> k=2q+1) with CONFLICT-FREE pads:
//   A stride 24 floats: LDS.64 banks (24*gq + 2qq) mod 32 distinct per phase.
//   B stride 132 floats: banks (8qq + gq) mod 32 distinct across the warp.
#define NSTG 5
#define AST  24
#define BST  132

template <int BM, int WN, bool DOGELU, bool ROUND, bool GROUPED>
__global__ void __launch_bounds__(128, (BM == 128) ? 2 : 3)
mma_gemm(const float* __restrict__ Abase, const float* __restrict__ Ball,
         const float* __restrict__ biasall, float* __restrict__ Cbase,
         const int* __restrict__ counts, const int* __restrict__ bases,
         int M_in, int N, int K) {
    constexpr int NT = WN / 8;
    constexpr int ACH = BM / 32;
    constexpr int ASTF = BM * AST;
    constexpr int STGF = ASTF + 16 * BST;
    constexpr int STGB = STGF * 4;

    int e = GROUPED ? blockIdx.z : 0;
    int M = GROUPED ? counts[e] : M_in;
    int m0 = blockIdx.y * BM;
    if (m0 >= M) return;
    int n0 = blockIdx.x * 128;
    const float* A = GROUPED ? Abase + (size_t)bases[e] * K : Abase;
    const float* B = GROUPED ? Ball + (size_t)e * (size_t)K * N : Ball;
    const float* bias = GROUPED ? biasall + (size_t)e * N : biasall;
    float* C = GROUPED ? Cbase + (size_t)bases[e] * N : Cbase;

    extern __shared__ float smf[];
    uint32_t sbase = smem_u32(smf);
    int tid = threadIdx.x;
    int wid = tid >> 5, lane = tid & 31;
    int gq = lane >> 2, qq = lane & 3;
    int m0w = (BM == 128) ? (wid & 1) * 64 : 0;
    int n0w = (BM == 128) ? (wid >> 1) * 64 : wid * 32;

    int aq = tid & 3, ar = tid >> 2;
    int bq = tid & 31, br = tid >> 5;
    uint32_t adst[ACH], bdst[4];
    const float* asrc[ACH];
    const float* bsrc[4];
    uint32_t asz[ACH];
#pragma unroll
    for (int i = 0; i < ACH; i++) {
        int r = ar + 32 * i;
        adst[i] = (uint32_t)(r * (AST * 4) + aq * 16);
        int row = m0 + r;
        asz[i] = (row < M) ? 16u : 0u;
        asrc[i] = A + (size_t)((row < M) ? row : 0) * K + aq * 4;
    }
#pragma unroll
    for (int i = 0; i < 4; i++) {
        int rb = br + 4 * i;
        bdst[i] = (uint32_t)(ASTF * 4 + rb * (BST * 4) + bq * 16);
        bsrc[i] = B + (size_t)rb * N + n0 + bq * 4;
    }

    const int NC = K / 16;

    float acc[4][NT][4];
#pragma unroll
    for (int i = 0; i < 4; i++)
#pragma unroll
        for (int j = 0; j < NT; j++)
#pragma unroll
            for (int l = 0; l < 4; l++) acc[i][j][l] = 0.f;

    // prologue: stages 0,1,2
#pragma unroll
    for (int pk = 0; pk < 3; pk++) {
        uint32_t sb = sbase + pk * STGB;
        int k0 = pk * 16;
#pragma unroll
        for (int i = 0; i < ACH; i++) CP_ASYNC_CG(sb + adst[i], asrc[i] + k0, asz[i]);
#pragma unroll
        for (int i = 0; i < 4; i++) CP_ASYNC_CG(sb + bdst[i], bsrc[i] + (size_t)k0 * N, 16u);
        CP_COMMIT();
    }
    CP_WAIT2();            // stage 0 resident
    __syncthreads();

    // fragment double buffers
    uint32_t a0[4][4], b0[NT][2], a1[4][4], b1[NT][2];

#define LOADFRAG(AF, BF, ASP, BSP, KK)                                         \
    do {                                                                       \
        _Pragma("unroll")                                                      \
        for (int mt = 0; mt < 4; mt++) {                                       \
            int r = m0w + mt * 16 + gq;                                        \
            float2 av0 = *(const float2*)&(ASP)[r * AST + (KK) + 2 * qq];      \
            float2 av1 = *(const float2*)&(ASP)[(r + 8) * AST + (KK) + 2 * qq];\
            AF[mt][0] = __float_as_uint(av0.x);                                \
            AF[mt][1] = __float_as_uint(av1.x);                                \
            AF[mt][2] = __float_as_uint(av0.y);                                \
            AF[mt][3] = __float_as_uint(av1.y);                                \
        }                                                                      \
        _Pragma("unroll")                                                      \
        for (int nt = 0; nt < NT; nt++) {                                      \
            int c = n0w + nt * 8 + gq;                                         \
            BF[nt][0] = __float_as_uint((BSP)[((KK) + 2 * qq) * BST + c]);     \
            BF[nt][1] = __float_as_uint((BSP)[((KK) + 2 * qq + 1) * BST + c]); \
        }                                                                      \
    } while (0)

#define MMAALL(AF, BF)                                                        \
    do {                                                                      \
        _Pragma("unroll")                                                     \
        for (int mt = 0; mt < 4; mt++)                                        \
            _Pragma("unroll")                                                 \
            for (int nt = 0; nt < NT; nt++)                                   \
                mma_tf32(acc[mt][nt], AF[mt], BF[nt]);                        \
    } while (0)

    {
        const float* As0 = smf;
        const float* Bs0 = smf + ASTF;
        LOADFRAG(a0, b0, As0, Bs0, 0);
    }

    int sc = 0;   // slot of stage kc
    for (int kc = 0; kc < NC; kc++) {
        // issue stage kc+3 into slot (sc+3)%5 (held stage kc-2; reads finished
        // at iter kc-2, separated from this write by barrier at iter kc-1)
        if (kc + 3 < NC) {
            int si = sc + 3; if (si >= NSTG) si -= NSTG;
            uint32_t sb = sbase + si * STGB;
            int k0 = (kc + 3) * 16;
#pragma unroll
            for (int i = 0; i < ACH; i++) CP_ASYNC_CG(sb + adst[i], asrc[i] + k0, asz[i]);
#pragma unroll
            for (int i = 0; i < 4; i++) CP_ASYNC_CG(sb + bdst[i], bsrc[i] + (size_t)k0 * N, 16u);
        }
        CP_COMMIT();
        CP_WAIT2();        // groups <= kc+1 complete -> stages kc, kc+1 resident
        __syncthreads();

        const float* Asc = smf + sc * STGF;
        const float* Bsc = Asc + ASTF;
        int sn = (kc + 1 < NC) ? ((sc + 1 == NSTG) ? 0 : sc + 1) : sc;
        const float* Asn = smf + sn * STGF;
        const float* Bsn = Asn + ASTF;

        LOADFRAG(a1, b1, Asc, Bsc, 8);   // prefetch k8=1 of this stage
        MMAALL(a0, b0);                  // compute k8=0
        LOADFRAG(a0, b0, Asn, Bsn, 0);   // prefetch k8=0 of next stage
        MMAALL(a1, b1);                  // compute k8=1

        sc = (sc + 1 == NSTG) ? 0 : sc + 1;
    }
#undef LOADFRAG
#undef MMAALL

    // epilogue
#pragma unroll
    for (int mt = 0; mt < 4; mt++) {
        int row0 = m0 + m0w + mt * 16 + gq;
        int row1 = row0 + 8;
#pragma unroll
        for (int nt = 0; nt < NT; nt++) {
            int col = n0 + n0w + nt * 8 + 2 * qq;
            float bb0 = bias[col], bb1 = bias[col + 1];
            float v0 = acc[mt][nt][0] + bb0;
            float v1 = acc[mt][nt][1] + bb1;
            float v2 = acc[mt][nt][2] + bb0;
            float v3 = acc[mt][nt][3] + bb1;
            if (DOGELU) { v0 = gelu_f(v0); v1 = gelu_f(v1); v2 = gelu_f(v2); v3 = gelu_f(v3); }
            if (ROUND)  { v0 = to_tf32(v0); v1 = to_tf32(v1); v2 = to_tf32(v2); v3 = to_tf32(v3); }
            if (row0 < M) *(float2*)(C + (size_t)row0 * N + col) = make_float2(v0, v1);
            if (row1 < M) *(float2*)(C + (size_t)row1 * N + col) = make_float2(v2, v3);
        }
    }
}

#define SMEM_BIG   (NSTG * (128 * AST + 16 * BST) * 4)
#define SMEM_SMALL (NSTG * (64 * AST + 16 * BST) * 4)

// ---------------- launch ----------------
extern "C" void kernel_launch(void* const* d_in, const int* in_sizes, int n_in,
                              void* d_out, int out_size) {
    const float* x      = (const float*)d_in[0];
    const float* r_ln_g = (const float*)d_in[1];
    const float* r_ln_b = (const float*)d_in[2];
    const float* r_w1   = (const float*)d_in[3];
    const float* r_b1   = (const float*)d_in[4];
    const float* r_w2   = (const float*)d_in[5];
    const float* r_b2   = (const float*)d_in[6];
    const float* temp   = (const float*)d_in[7];
    const float* e_ln_g = (const float*)d_in[8];
    const float* e_ln_b = (const float*)d_in[9];
    const float* e_w1   = (const float*)d_in[10];
    const float* e_b1   = (const float*)d_in[11];
    const float* e_w2   = (const float*)d_in[12];
    const float* e_b2   = (const float*)d_in[13];
    const float* c_ln_g = (const float*)d_in[14];
    const float* c_ln_b = (const float*)d_in[15];
    const float* c_w1   = (const float*)d_in[16];
    const float* c_b1   = (const float*)d_in[17];
    const float* c_w2   = (const float*)d_in[18];
    const float* c_b2   = (const float*)d_in[19];
    const float* o_ln_g = (const float*)d_in[20];
    const float* o_ln_b = (const float*)d_in[21];
    float* out = (float*)d_out;

    float *p_h, *p_xhat, *p_r, *p_rh, *p_tg, *p_y, *p_f1, *p_f2, *p_cln, *p_ch, *p_co;
    int *p_counts, *p_base, *p_perm, *p_te, *p_tp;
    cudaGetSymbolAddress((void**)&p_h, g_h);
    cudaGetSymbolAddress((void**)&p_xhat, g_xhat);
    cudaGetSymbolAddress((void**)&p_r, g_r);
    cudaGetSymbolAddress((void**)&p_rh, g_rh);
    cudaGetSymbolAddress((void**)&p_counts, g_counts);
    cudaGetSymbolAddress((void**)&p_base, g_base);
    cudaGetSymbolAddress((void**)&p_perm, g_perm);
    cudaGetSymbolAddress((void**)&p_te, g_te);
    cudaGetSymbolAddress((void**)&p_tp, g_tp);
    cudaGetSymbolAddress((void**)&p_tg, g_tg);
    cudaGetSymbolAddress((void**)&p_y, g_y);
    cudaGetSymbolAddress((void**)&p_f1, g_f1);
    cudaGetSymbolAddress((void**)&p_f2, g_f2);
    cudaGetSymbolAddress((void**)&p_cln, g_cln);
    cudaGetSymbolAddress((void**)&p_ch, g_ch);
    cudaGetSymbolAddress((void**)&p_co, g_co);

    cudaFuncSetAttribute(mma_gemm<128, 64, true,  false, false>, cudaFuncAttributeMaxDynamicSharedMemorySize, SMEM_BIG);
    cudaFuncSetAttribute(mma_gemm<128, 64, true,  true,  true >, cudaFuncAttributeMaxDynamicSharedMemorySize, SMEM_BIG);
    cudaFuncSetAttribute(mma_gemm<128, 64, false, false, true >, cudaFuncAttributeMaxDynamicSharedMemorySize, SMEM_BIG);
    cudaFuncSetAttribute(mma_gemm<128, 64, true,  true,  false>, cudaFuncAttributeMaxDynamicSharedMemorySize, SMEM_BIG);
    cudaFuncSetAttribute(mma_gemm<64,  32, false, false, false>, cudaFuncAttributeMaxDynamicSharedMemorySize, SMEM_SMALL);

    // 0. zero expert counts
    zero_counts_kernel<<<1, 32>>>(p_counts);
    // 1+2. h = x + pos; shared LN -> xhat; router input r (tf32)
    posln_kernel<<<NTOK / 8, 256>>>(x, r_ln_g, r_ln_b, p_h, p_xhat, p_r);
    // 3. router hidden: rh = gelu(r @ r_w1 + r_b1)
    mma_gemm<128, 64, true, false, false><<<dim3(H / 128, NTOK / 128), 128, SMEM_BIG>>>(
        p_r, r_w1, r_b1, p_rh, nullptr, nullptr, NTOK, H, D);
    // 4. router logits -> top2 -> compaction (2 warps/token)
    router_kernel<<<NTOK / 4, 256>>>(p_rh, r_w2, r_b2, temp, p_counts, p_perm, p_te, p_tp, p_tg);
    // 5. prefix sums
    base_kernel<<<1, 1>>>(p_counts, p_base);
    // 6. gather expert inputs (per-expert LN affine, tf32)
    gather_kernel<<<dim3(NTOK / 8, E), 256>>>(p_xhat, e_ln_g, e_ln_b, p_counts, p_base, p_perm, p_y);
    // 7. expert FFN layer 1
    mma_gemm<128, 64, true, true, true><<<dim3(HE / 128, NTOK / 128, E), 128, SMEM_BIG>>>(
        p_y, e_w1, e_b1, p_f1, p_counts, p_base, 0, HE, D);
    // 8. expert FFN layer 2
    mma_gemm<128, 64, false, false, true><<<dim3(D / 128, NTOK / 128, E), 128, SMEM_BIG>>>(
        p_f1, e_w2, e_b2, p_f2, p_counts, p_base, 0, D, HE);
    // 9+10. combine (gates) + combiner LN fused
    combine_ln_kernel<<<NTOK / 8, 256>>>(p_f2, p_base, p_te, p_tp, p_tg, c_ln_g, c_ln_b, p_cln);
    // 11. combiner MLP (gemm2 uses BM=64 variant: 256 CTAs, balanced waves)
    mma_gemm<128, 64, true, true, false><<<dim3(2 * D / 128, NTOK / 128), 128, SMEM_BIG>>>(
        p_cln, c_w1, c_b1, p_ch, nullptr, nullptr, NTOK, 2 * D, D);
    mma_gemm<64, 32, false, false, false><<<dim3(D / 128, NTOK / 64), 128, SMEM_SMALL>>>(
        p_ch, c_w2, c_b2, p_co, nullptr, nullptr, NTOK, D, 2 * D);
    // 12. out = LN(h + co)
    lnout_kernel<<<NTOK / 8, 256>>>(p_h, p_co, o_ln_g, o_ln_b, out);
}

// round 13
// speedup vs baseline: 1.2385x; 1.0538x over previous
#include <cuda_runtime.h>
#include <cstdint>
#include <math.h>

// ---------------- problem constants ----------------
#define NTOK 2048      // B*S
#define D    1024
#define H    4096
#define HE   4096
#define E    8
#define LN_EPS 1e-5f
#define NLB  (H / 128)   // 32 logit partial blocks

// ---------------- scratch (device globals) ----------------
__device__ float g_h    [NTOK * D];
__device__ float g_xhat [NTOK * D];
__device__ float g_r    [NTOK * D];
__device__ float g_lgp  [NTOK * NLB * E];   // logit partials [token][block][expert]
__device__ int   g_counts[E];
__device__ int   g_base  [E];
__device__ int   g_perm  [E * NTOK];
__device__ int   g_te   [NTOK * 2];
__device__ int   g_tp   [NTOK * 2];
__device__ float g_tg   [NTOK * 2];
__device__ float g_y    [2 * NTOK * D];
__device__ float g_f1   [2 * NTOK * HE];
__device__ float g_f2   [2 * NTOK * D];
__device__ float g_cln  [NTOK * D];
__device__ float g_ch   [NTOK * 2 * D];
__device__ float g_co   [NTOK * D];

// ---------------- helpers ----------------
__device__ __forceinline__ float gelu_f(float x) {
    return 0.5f * x * (1.0f + erff(x * 0.7071067811865475f));
}
__device__ __forceinline__ float to_tf32(float x) {
    uint32_t u;
    asm("cvt.rna.tf32.f32 %0, %1;" : "=r"(u) : "f"(x));
    return __uint_as_float(u);
}
__device__ __forceinline__ uint32_t smem_u32(const void* p) {
    uint32_t a;
    asm("{ .reg .u64 t; cvta.to.shared.u64 t, %1; cvt.u32.u64 %0, t; }" : "=r"(a) : "l"(p));
    return a;
}
__device__ __forceinline__ float warp_sum(float v) {
#pragma unroll
    for (int o = 16; o; o >>= 1) v += __shfl_xor_sync(0xffffffffu, v, o);
    return v;
}

// cp.async (baseline PTX, compute_80+)
#define CP_ASYNC_CG(dst, src, srcsz) \
    asm volatile("cp.async.cg.shared.global [%0], [%1], 16, %2;" \
        :: "r"(dst), "l"(src), "r"(srcsz) : "memory")
#define CP_COMMIT() asm volatile("cp.async.commit_group;" ::: "memory")
#define CP_WAIT2()  asm volatile("cp.async.wait_group 2;" ::: "memory")

__device__ __forceinline__ void mma_tf32(float* c, const uint32_t* a, const uint32_t* b) {
    asm volatile(
        "mma.sync.aligned.m16n8k8.row.col.f32.tf32.tf32.f32 "
        "{%0,%1,%2,%3}, {%4,%5,%6,%7}, {%8,%9}, {%0,%1,%2,%3};"
        : "+f"(c[0]), "+f"(c[1]), "+f"(c[2]), "+f"(c[3])
        : "r"(a[0]), "r"(a[1]), "r"(a[2]), "r"(a[3]), "r"(b[0]), "r"(b[1]));
}

// ---------------- elementwise (warp-per-token) ----------------
__global__ void zero_counts_kernel(int* counts) {
    if (threadIdx.x < E) counts[threadIdx.x] = 0;
}

// h = x + pos; LN(h) -> xhat (no affine); r = tf32(xhat*g+b)
__global__ void posln_kernel(const float* __restrict__ x,
                             const float* __restrict__ g, const float* __restrict__ b,
                             float* __restrict__ h, float* __restrict__ xhat,
                             float* __restrict__ r) {
    int wid = threadIdx.x >> 5, lane = threadIdx.x & 31;
    int t = blockIdx.x * 8 + wid;
    int sp = t & 1023;
    const float LOG1E4 = 9.210340371976184f;
    const float4* xr = (const float4*)(x + (size_t)t * D);
    float4 v[8];
    float s = 0.f;
#pragma unroll
    for (int j = 0; j < 8; j++) {
        int idx = j * 32 + lane;
        float4 val = xr[idx];
        int d0 = idx * 4;
        float a0 = (float)sp * expf(-LOG1E4 * (float)d0 * (1.f / (float)D));
        float a1 = (float)sp * expf(-LOG1E4 * (float)(d0 + 2) * (1.f / (float)D));
        float s0, c0, s1, c1;
        sincosf(a0, &s0, &c0);
        sincosf(a1, &s1, &c1);
        val.x += s0; val.y += c0;
        val.z += s1; val.w += c1;
        v[j] = val;
        s += val.x + val.y + val.z + val.w;
    }
    float mean = warp_sum(s) * (1.f / (float)D);
    float q = 0.f;
#pragma unroll
    for (int j = 0; j < 8; j++) {
        float dx = v[j].x - mean, dy = v[j].y - mean, dz = v[j].z - mean, dw = v[j].w - mean;
        q += dx * dx + dy * dy + dz * dz + dw * dw;
    }
    float rstd = rsqrtf(warp_sum(q) * (1.f / (float)D) + LN_EPS);
    float4* hr = (float4*)(h + (size_t)t * D);
    float4* xh = (float4*)(xhat + (size_t)t * D);
    float4* rr = (float4*)(r + (size_t)t * D);
    const float4* g4 = (const float4*)g;
    const float4* b4 = (const float4*)b;
#pragma unroll
    for (int j = 0; j < 8; j++) {
        int idx = j * 32 + lane;
        float4 val = v[j];
        hr[idx] = val;
        float4 xo;
        xo.x = (val.x - mean) * rstd; xo.y = (val.y - mean) * rstd;
        xo.z = (val.z - mean) * rstd; xo.w = (val.w - mean) * rstd;
        xh[idx] = xo;
        float4 gg = g4[idx], bb = b4[idx], ro;
        ro.x = to_tf32(xo.x * gg.x + bb.x); ro.y = to_tf32(xo.y * gg.y + bb.y);
        ro.z = to_tf32(xo.z * gg.z + bb.z); ro.w = to_tf32(xo.w * gg.w + bb.w);
        rr[idx] = ro;
    }
}

// out = LN(h + co) * g + b
__global__ void lnout_kernel(const float* __restrict__ X, const float* __restrict__ X2,
                             const float* __restrict__ g, const float* __restrict__ b,
                             float* __restrict__ out) {
    int wid = threadIdx.x >> 5, lane = threadIdx.x & 31;
    int t = blockIdx.x * 8 + wid;
    const float4* xr = (const float4*)(X + (size_t)t * D);
    const float4* x2 = (const float4*)(X2 + (size_t)t * D);
    float4 v[8];
    float s = 0.f;
#pragma unroll
    for (int j = 0; j < 8; j++) {
        int idx = j * 32 + lane;
        float4 a = xr[idx], c = x2[idx];
        a.x += c.x; a.y += c.y; a.z += c.z; a.w += c.w;
        v[j] = a;
        s += a.x + a.y + a.z + a.w;
    }
    float mean = warp_sum(s) * (1.f / (float)D);
    float q = 0.f;
#pragma unroll
    for (int j = 0; j < 8; j++) {
        float dx = v[j].x - mean, dy = v[j].y - mean, dz = v[j].z - mean, dw = v[j].w - mean;
        q += dx * dx + dy * dy + dz * dz + dw * dw;
    }
    float rstd = rsqrtf(warp_sum(q) * (1.f / (float)D) + LN_EPS);
    float4* o4 = (float4*)(out + (size_t)t * D);
    const float4* g4 = (const float4*)g;
    const float4* b4 = (const float4*)b;
#pragma unroll
    for (int j = 0; j < 8; j++) {
        int idx = j * 32 + lane;
        float4 gg = g4[idx], bb = b4[idx], o;
        o.x = (v[j].x - mean) * rstd * gg.x + bb.x;
        o.y = (v[j].y - mean) * rstd * gg.y + bb.y;
        o.z = (v[j].z - mean) * rstd * gg.z + bb.z;
        o.w = (v[j].w - mean) * rstd * gg.w + bb.w;
        o4[idx] = o;
    }
}

// combined = g1*f2[row1] + g2*f2[row2]; cln = tf32(LN(combined)*g+b)
__global__ void combine_ln_kernel(const float* __restrict__ f2, const int* __restrict__ bases,
                                  const int* __restrict__ te, const int* __restrict__ tp,
                                  const float* __restrict__ tg,
                                  const float* __restrict__ g, const float* __restrict__ b,
                                  float* __restrict__ cln) {
    int wid = threadIdx.x >> 5, lane = threadIdx.x & 31;
    int t = blockIdx.x * 8 + wid;
    int e1 = te[2 * t], e2 = te[2 * t + 1];
    int p1 = tp[2 * t], p2 = tp[2 * t + 1];
    float g1 = tg[2 * t], g2 = tg[2 * t + 1];
    const float4* r1 = (const float4*)(f2 + (size_t)(bases[e1] + p1) * D);
    const float4* r2 = (const float4*)(f2 + (size_t)(bases[e2] + p2) * D);
    float4 v[8];
    float s = 0.f;
#pragma unroll
    for (int j = 0; j < 8; j++) {
        int idx = j * 32 + lane;
        float4 a = r1[idx], c = r2[idx], o;
        o.x = g1 * a.x + g2 * c.x; o.y = g1 * a.y + g2 * c.y;
        o.z = g1 * a.z + g2 * c.z; o.w = g1 * a.w + g2 * c.w;
        v[j] = o;
        s += o.x + o.y + o.z + o.w;
    }
    float mean = warp_sum(s) * (1.f / (float)D);
    float q = 0.f;
#pragma unroll
    for (int j = 0; j < 8; j++) {
        float dx = v[j].x - mean, dy = v[j].y - mean, dz = v[j].z - mean, dw = v[j].w - mean;
        q += dx * dx + dy * dy + dz * dz + dw * dw;
    }
    float rstd = rsqrtf(warp_sum(q) * (1.f / (float)D) + LN_EPS);
    float4* o4 = (float4*)(cln + (size_t)t * D);
    const float4* g4 = (const float4*)g;
    const float4* b4 = (const float4*)b;
#pragma unroll
    for (int j = 0; j < 8; j++) {
        int idx = j * 32 + lane;
        float4 gg = g4[idx], bb = b4[idx], o;
        o.x = to_tf32((v[j].x - mean) * rstd * gg.x + bb.x);
        o.y = to_tf32((v[j].y - mean) * rstd * gg.y + bb.y);
        o.z = to_tf32((v[j].z - mean) * rstd * gg.z + bb.z);
        o.w = to_tf32((v[j].w - mean) * rstd * gg.w + bb.w);
        o4[idx] = o;
    }
}

// gather: y[base[e]+i] = tf32(xhat[perm]*eg+eb)
__global__ void gather_kernel(const float* __restrict__ xhat, const float* __restrict__ elng,
                              const float* __restrict__ elnb, const int* __restrict__ counts,
                              const int* __restrict__ bases, const int* __restrict__ perm,
                              float* __restrict__ y) {
    int wid = threadIdx.x >> 5, lane = threadIdx.x & 31;
    int e = blockIdx.y;
    int i = blockIdx.x * 8 + wid;
    if (i >= counts[e]) return;
    int t = perm[e * NTOK + i];
    const float4* src = (const float4*)(xhat + (size_t)t * D);
    const float4* g4 = (const float4*)(elng + (size_t)e * D);
    const float4* b4 = (const float4*)(elnb + (size_t)e * D);
    float4* dst = (float4*)(y + (size_t)(bases[e] + i) * D);
#pragma unroll
    for (int j = 0; j < 8; j++) {
        int idx = j * 32 + lane;
        float4 s = src[idx], gg = g4[idx], bb = b4[idx], o;
        o.x = to_tf32(s.x * gg.x + bb.x); o.y = to_tf32(s.y * gg.y + bb.y);
        o.z = to_tf32(s.z * gg.z + bb.z); o.w = to_tf32(s.w * gg.w + bb.w);
        dst[idx] = o;
    }
}

// router reduce: warp per token. lgp[t][32][8] contiguous 1KB -> coalesced.
// lane l holds partial block l (8 floats); xor-tree sums across lanes;
// lane 0 does temperature softmax, top-2, compaction.
__global__ void router_top2_kernel(const float* __restrict__ lgp,
                                   const float* __restrict__ b2, const float* __restrict__ temp,
                                   int* __restrict__ counts, int* __restrict__ perm,
                                   int* __restrict__ te, int* __restrict__ tp,
                                   float* __restrict__ tg) {
    int wid = threadIdx.x >> 5, lane = threadIdx.x & 31;
    int t = blockIdx.x * 8 + wid;
    const float4* src = (const float4*)(lgp + (size_t)t * (NLB * E) + lane * 8);
    float4 va = src[0], vb = src[1];
    float v[E] = {va.x, va.y, va.z, va.w, vb.x, vb.y, vb.z, vb.w};
#pragma unroll
    for (int o = 16; o; o >>= 1)
#pragma unroll
        for (int e = 0; e < E; e++) v[e] += __shfl_xor_sync(0xffffffffu, v[e], o);
    if (lane == 0) {
        float invt = 1.0f / temp[0];
        float p[E];
        float mx = -1e30f;
#pragma unroll
        for (int e = 0; e < E; e++) { p[e] = (v[e] + b2[e]) * invt; mx = fmaxf(mx, p[e]); }
        float se = 0.f;
#pragma unroll
        for (int e = 0; e < E; e++) { p[e] = expf(p[e] - mx); se += p[e]; }
        float inv = 1.0f / se;
#pragma unroll
        for (int e = 0; e < E; e++) p[e] *= inv;
        int i1 = 0;
#pragma unroll
        for (int e = 1; e < E; e++) if (p[e] > p[i1]) i1 = e;
        int i2 = (i1 == 0) ? 1 : 0;
#pragma unroll
        for (int e = 0; e < E; e++) if (e != i1 && p[e] > p[i2]) i2 = e;
        int pos1 = atomicAdd(&counts[i1], 1);
        perm[i1 * NTOK + pos1] = t;
        int pos2 = atomicAdd(&counts[i2], 1);
        perm[i2 * NTOK + pos2] = t;
        te[2 * t] = i1; tp[2 * t] = pos1; tg[2 * t] = p[i1];
        te[2 * t + 1] = i2; tp[2 * t + 1] = pos2; tg[2 * t + 1] = p[i2];
    }
}

__global__ void base_kernel(const int* __restrict__ counts, int* __restrict__ bases) {
    int s = 0;
    for (int e = 0; e < E; e++) { bases[e] = s; s += counts[e]; }
}

// ---------------- tf32 mma.sync GEMM (R10 core; optional fused logits) ------
// C[M,N] = act(A[M,K] @ B[K,N] + bias[N]); A K-contig, B N-contig.
// BM in {128,64}, BN=128, BK=16, 128 threads (4 warps), FIVE-stage cp.async.
// Issue-first ordering; 5 stages -> overwrite provably barrier-separated.
// LOGITS mode (GEMM1 only): do NOT store C; contract post-GELU tile with
// w2[n0:n0+128, 0:8] into per-CTA logit partials (smem atomic pair per cell
// is a commutative 2-add onto zero -> bit-deterministic), write to lgp.
#define NSTG 5

template <int BM, int WN, bool DOGELU, bool ROUND, bool GROUPED, bool LOGITS>
__global__ void __launch_bounds__(128, (BM == 128) ? 2 : 3)
mma_gemm(const float* __restrict__ Abase, const float* __restrict__ Ball,
         const float* __restrict__ biasall, float* __restrict__ Cbase,
         const int* __restrict__ counts, const int* __restrict__ bases,
         int M_in, int N, int K,
         const float* __restrict__ w2, float* __restrict__ lgp) {
    constexpr int NT = WN / 8;
    constexpr int ACH = BM / 32;
    constexpr int ASTF = BM * 20;
    constexpr int STGF = ASTF + 16 * 136;
    constexpr int STGB = STGF * 4;

    int e = GROUPED ? blockIdx.z : 0;
    int M = GROUPED ? counts[e] : M_in;
    int m0 = blockIdx.y * BM;
    if (m0 >= M) return;
    int n0 = blockIdx.x * 128;
    const float* A = GROUPED ? Abase + (size_t)bases[e] * K : Abase;
    const float* B = GROUPED ? Ball + (size_t)e * (size_t)K * N : Ball;
    const float* bias = GROUPED ? biasall + (size_t)e * N : biasall;
    float* C = GROUPED ? Cbase + (size_t)bases[e] * N : Cbase;

    extern __shared__ float smf[];
    uint32_t sbase = smem_u32(smf);
    int tid = threadIdx.x;
    int wid = tid >> 5, lane = tid & 31;
    int gq = lane >> 2, qq = lane & 3;
    int m0w = (BM == 128) ? (wid & 1) * 64 : 0;
    int n0w = (BM == 128) ? (wid >> 1) * 64 : wid * 32;

    int aq = tid & 3, ar = tid >> 2;
    int bq = tid & 31, br = tid >> 5;
    uint32_t adst[ACH], bdst[4];
    const float* asrc[ACH];
    const float* bsrc[4];
    uint32_t asz[ACH];
#pragma unroll
    for (int i = 0; i < ACH; i++) {
        int r = ar + 32 * i;
        adst[i] = (uint32_t)(r * 80 + aq * 16);
        int row = m0 + r;
        asz[i] = (row < M) ? 16u : 0u;
        asrc[i] = A + (size_t)((row < M) ? row : 0) * K + aq * 4;
    }
#pragma unroll
    for (int i = 0; i < 4; i++) {
        int rb = br + 4 * i;
        bdst[i] = (uint32_t)(ASTF * 4 + rb * 544 + bq * 16);
        bsrc[i] = B + (size_t)rb * N + n0 + bq * 4;
    }

    const int NC = K / 16;

    float acc[4][NT][4];
#pragma unroll
    for (int i = 0; i < 4; i++)
#pragma unroll
        for (int j = 0; j < NT; j++)
#pragma unroll
            for (int l = 0; l < 4; l++) acc[i][j][l] = 0.f;

    // prologue: stages 0,1,2
#pragma unroll
    for (int pk = 0; pk < 3; pk++) {
        uint32_t sb = sbase + pk * STGB;
        int k0 = pk * 16;
#pragma unroll
        for (int i = 0; i < ACH; i++) CP_ASYNC_CG(sb + adst[i], asrc[i] + k0, asz[i]);
#pragma unroll
        for (int i = 0; i < 4; i++) CP_ASYNC_CG(sb + bdst[i], bsrc[i] + (size_t)k0 * N, 16u);
        CP_COMMIT();
    }
    CP_WAIT2();
    __syncthreads();

    uint32_t a0[4][4], b0[NT][2], a1[4][4], b1[NT][2];

#define LOADFRAG(AF, BF, ASP, BSP, KK)                                        \
    do {                                                                      \
        _Pragma("unroll")                                                     \
        for (int mt = 0; mt < 4; mt++) {                                      \
            int r = m0w + mt * 16 + gq;                                       \
            AF[mt][0] = __float_as_uint((ASP)[r * 20 + (KK) + qq]);           \
            AF[mt][1] = __float_as_uint((ASP)[(r + 8) * 20 + (KK) + qq]);     \
            AF[mt][2] = __float_as_uint((ASP)[r * 20 + (KK) + qq + 4]);       \
            AF[mt][3] = __float_as_uint((ASP)[(r + 8) * 20 + (KK) + qq + 4]); \
        }                                                                     \
        _Pragma("unroll")                                                     \
        for (int nt = 0; nt < NT; nt++) {                                     \
            int c = n0w + nt * 8 + gq;                                        \
            BF[nt][0] = __float_as_uint((BSP)[((KK) + qq) * 136 + c]);        \
            BF[nt][1] = __float_as_uint((BSP)[((KK) + qq + 4) * 136 + c]);    \
        }                                                                     \
    } while (0)

#define MMAALL(AF, BF)                                                        \
    do {                                                                      \
        _Pragma("unroll")                                                     \
        for (int mt = 0; mt < 4; mt++)                                        \
            _Pragma("unroll")                                                 \
            for (int nt = 0; nt < NT; nt++)                                   \
                mma_tf32(acc[mt][nt], AF[mt], BF[nt]);                        \
    } while (0)

    {
        const float* As0 = smf;
        const float* Bs0 = smf + ASTF;
        LOADFRAG(a0, b0, As0, Bs0, 0);
    }

    int sc = 0;
    for (int kc = 0; kc < NC; kc++) {
        if (kc + 3 < NC) {
            int si = sc + 3; if (si >= NSTG) si -= NSTG;
            uint32_t sb = sbase + si * STGB;
            int k0 = (kc + 3) * 16;
#pragma unroll
            for (int i = 0; i < ACH; i++) CP_ASYNC_CG(sb + adst[i], asrc[i] + k0, asz[i]);
#pragma unroll
            for (int i = 0; i < 4; i++) CP_ASYNC_CG(sb + bdst[i], bsrc[i] + (size_t)k0 * N, 16u);
        }
        CP_COMMIT();
        CP_WAIT2();
        __syncthreads();

        const float* Asc = smf + sc * STGF;
        const float* Bsc = Asc + ASTF;
        int sn = (kc + 1 < NC) ? ((sc + 1 == NSTG) ? 0 : sc + 1) : sc;
        const float* Asn = smf + sn * STGF;
        const float* Bsn = Asn + ASTF;

        LOADFRAG(a1, b1, Asc, Bsc, 8);
        MMAALL(a0, b0);
        LOADFRAG(a0, b0, Asn, Bsn, 0);
        MMAALL(a1, b1);

        sc = (sc + 1 == NSTG) ? 0 : sc + 1;
    }
#undef LOADFRAG
#undef MMAALL

    // ---------------- epilogue ----------------
    float* lgs = smf + NSTG * STGF;   // [128][8] logits scratch (LOGITS only)
    if (LOGITS) {
#pragma unroll
        for (int i = 0; i < 8; i++) lgs[i * 128 + tid] = 0.f;
        __syncthreads();
    }

#pragma unroll
    for (int mt = 0; mt < 4; mt++) {
        int row0 = m0 + m0w + mt * 16 + gq;
        int row1 = row0 + 8;
        float lg0[E], lg1[E];
        if (LOGITS) {
#pragma unroll
            for (int ee = 0; ee < E; ee++) { lg0[ee] = 0.f; lg1[ee] = 0.f; }
        }
#pragma unroll
        for (int nt = 0; nt < NT; nt++) {
            int col = n0 + n0w + nt * 8 + 2 * qq;
            float bb0 = bias[col], bb1 = bias[col + 1];
            float v0 = acc[mt][nt][0] + bb0;
            float v1 = acc[mt][nt][1] + bb1;
            float v2 = acc[mt][nt][2] + bb0;
            float v3 = acc[mt][nt][3] + bb1;
            if (DOGELU) { v0 = gelu_f(v0); v1 = gelu_f(v1); v2 = gelu_f(v2); v3 = gelu_f(v3); }
            if (LOGITS) {
                const float4* wr0 = (const float4*)(w2 + (size_t)col * E);
                float4 wa = wr0[0], wb = wr0[1];
                const float4* wr1 = (const float4*)(w2 + (size_t)(col + 1) * E);
                float4 wc = wr1[0], wd = wr1[1];
                lg0[0] += v0 * wa.x + v1 * wc.x; lg0[1] += v0 * wa.y + v1 * wc.y;
                lg0[2] += v0 * wa.z + v1 * wc.z; lg0[3] += v0 * wa.w + v1 * wc.w;
                lg0[4] += v0 * wb.x + v1 * wd.x; lg0[5] += v0 * wb.y + v1 * wd.y;
                lg0[6] += v0 * wb.z + v1 * wd.z; lg0[7] += v0 * wb.w + v1 * wd.w;
                lg1[0] += v2 * wa.x + v3 * wc.x; lg1[1] += v2 * wa.y + v3 * wc.y;
                lg1[2] += v2 * wa.z + v3 * wc.z; lg1[3] += v2 * wa.w + v3 * wc.w;
                lg1[4] += v2 * wb.x + v3 * wd.x; lg1[5] += v2 * wb.y + v3 * wd.y;
                lg1[6] += v2 * wb.z + v3 * wd.z; lg1[7] += v2 * wb.w + v3 * wd.w;
            } else {
                if (ROUND) { v0 = to_tf32(v0); v1 = to_tf32(v1); v2 = to_tf32(v2); v3 = to_tf32(v3); }
                if (row0 < M) *(float2*)(C + (size_t)row0 * N + col) = make_float2(v0, v1);
                if (row1 < M) *(float2*)(C + (size_t)row1 * N + col) = make_float2(v2, v3);
            }
        }
        if (LOGITS) {
            // reduce over the 4 qq lanes (lane bits 0..1)
#pragma unroll
            for (int off = 1; off <= 2; off <<= 1)
#pragma unroll
                for (int ee = 0; ee < E; ee++) {
                    lg0[ee] += __shfl_xor_sync(0xffffffffu, lg0[ee], off);
                    lg1[ee] += __shfl_xor_sync(0xffffffffu, lg1[ee], off);
                }
            if (qq == 0) {
                int r0 = m0w + mt * 16 + gq;   // CTA-local rows
                int r1 = r0 + 8;
#pragma unroll
                for (int ee = 0; ee < E; ee++) {
                    atomicAdd(&lgs[r0 * E + ee], lg0[ee]);   // exactly 2 adds/cell
                    atomicAdd(&lgs[r1 * E + ee], lg1[ee]);   // -> deterministic
                }
            }
        }
    }

    if (LOGITS) {
        __syncthreads();
        // write partials: lgp[(m0+row)][blockIdx.x][0..7]
        int row = tid;
        float4* dst = (float4*)(lgp + ((size_t)(m0 + row) * NLB + blockIdx.x) * E);
        const float4* src = (const float4*)&lgs[row * E];
        dst[0] = src[0];
        dst[1] = src[1];
    }
}

#define SMEM_BIG   (NSTG * (128 * 20 + 16 * 136) * 4)
#define SMEM_LOGIT (SMEM_BIG + 128 * E * 4)
#define SMEM_SMALL (NSTG * (64 * 20 + 16 * 136) * 4)

// ---------------- launch ----------------
extern "C" void kernel_launch(void* const* d_in, const int* in_sizes, int n_in,
                              void* d_out, int out_size) {
    const float* x      = (const float*)d_in[0];
    const float* r_ln_g = (const float*)d_in[1];
    const float* r_ln_b = (const float*)d_in[2];
    const float* r_w1   = (const float*)d_in[3];
    const float* r_b1   = (const float*)d_in[4];
    const float* r_w2   = (const float*)d_in[5];
    const float* r_b2   = (const float*)d_in[6];
    const float* temp   = (const float*)d_in[7];
    const float* e_ln_g = (const float*)d_in[8];
    const float* e_ln_b = (const float*)d_in[9];
    const float* e_w1   = (const float*)d_in[10];
    const float* e_b1   = (const float*)d_in[11];
    const float* e_w2   = (const float*)d_in[12];
    const float* e_b2   = (const float*)d_in[13];
    const float* c_ln_g = (const float*)d_in[14];
    const float* c_ln_b = (const float*)d_in[15];
    const float* c_w1   = (const float*)d_in[16];
    const float* c_b1   = (const float*)d_in[17];
    const float* c_w2   = (const float*)d_in[18];
    const float* c_b2   = (const float*)d_in[19];
    const float* o_ln_g = (const float*)d_in[20];
    const float* o_ln_b = (const float*)d_in[21];
    float* out = (float*)d_out;

    float *p_h, *p_xhat, *p_r, *p_lgp, *p_tg, *p_y, *p_f1, *p_f2, *p_cln, *p_ch, *p_co;
    int *p_counts, *p_base, *p_perm, *p_te, *p_tp;
    cudaGetSymbolAddress((void**)&p_h, g_h);
    cudaGetSymbolAddress((void**)&p_xhat, g_xhat);
    cudaGetSymbolAddress((void**)&p_r, g_r);
    cudaGetSymbolAddress((void**)&p_lgp, g_lgp);
    cudaGetSymbolAddress((void**)&p_counts, g_counts);
    cudaGetSymbolAddress((void**)&p_base, g_base);
    cudaGetSymbolAddress((void**)&p_perm, g_perm);
    cudaGetSymbolAddress((void**)&p_te, g_te);
    cudaGetSymbolAddress((void**)&p_tp, g_tp);
    cudaGetSymbolAddress((void**)&p_tg, g_tg);
    cudaGetSymbolAddress((void**)&p_y, g_y);
    cudaGetSymbolAddress((void**)&p_f1, g_f1);
    cudaGetSymbolAddress((void**)&p_f2, g_f2);
    cudaGetSymbolAddress((void**)&p_cln, g_cln);
    cudaGetSymbolAddress((void**)&p_ch, g_ch);
    cudaGetSymbolAddress((void**)&p_co, g_co);

    cudaFuncSetAttribute(mma_gemm<128, 64, true,  false, false, true >, cudaFuncAttributeMaxDynamicSharedMemorySize, SMEM_LOGIT);
    cudaFuncSetAttribute(mma_gemm<128, 64, true,  true,  true,  false>, cudaFuncAttributeMaxDynamicSharedMemorySize, SMEM_BIG);
    cudaFuncSetAttribute(mma_gemm<128, 64, false, false, true,  false>, cudaFuncAttributeMaxDynamicSharedMemorySize, SMEM_BIG);
    cudaFuncSetAttribute(mma_gemm<128, 64, true,  true,  false, false>, cudaFuncAttributeMaxDynamicSharedMemorySize, SMEM_BIG);
    cudaFuncSetAttribute(mma_gemm<64,  32, false, false, false, false>, cudaFuncAttributeMaxDynamicSharedMemorySize, SMEM_SMALL);

    // 0. zero expert counts
    zero_counts_kernel<<<1, 32>>>(p_counts);
    // 1+2. h = x + pos; shared LN -> xhat; router input r (tf32)
    posln_kernel<<<NTOK / 8, 256>>>(x, r_ln_g, r_ln_b, p_h, p_xhat, p_r);
    // 3. router GEMM1 with FUSED logit partials (no rh materialization)
    mma_gemm<128, 64, true, false, false, true><<<dim3(H / 128, NTOK / 128), 128, SMEM_LOGIT>>>(
        p_r, r_w1, r_b1, nullptr, nullptr, nullptr, NTOK, H, D, r_w2, p_lgp);
    // 4. reduce partials -> softmax -> top2 -> compaction
    router_top2_kernel<<<NTOK / 8, 256>>>(p_lgp, r_b2, temp, p_counts, p_perm, p_te, p_tp, p_tg);
    // 5. prefix sums
    base_kernel<<<1, 1>>>(p_counts, p_base);
    // 6. gather expert inputs (per-expert LN affine, tf32)
    gather_kernel<<<dim3(NTOK / 8, E), 256>>>(p_xhat, e_ln_g, e_ln_b, p_counts, p_base, p_perm, p_y);
    // 7. expert FFN layer 1
    mma_gemm<128, 64, true, true, true, false><<<dim3(HE / 128, NTOK / 128, E), 128, SMEM_BIG>>>(
        p_y, e_w1, e_b1, p_f1, p_counts, p_base, 0, HE, D, nullptr, nullptr);
    // 8. expert FFN layer 2
    mma_gemm<128, 64, false, false, true, false><<<dim3(D / 128, NTOK / 128, E), 128, SMEM_BIG>>>(
        p_f1, e_w2, e_b2, p_f2, p_counts, p_base, 0, D, HE, nullptr, nullptr);
    // 9+10. combine (gates) + combiner LN fused
    combine_ln_kernel<<<NTOK / 8, 256>>>(p_f2, p_base, p_te, p_tp, p_tg, c_ln_g, c_ln_b, p_cln);
    // 11. combiner MLP
    mma_gemm<128, 64, true, true, false, false><<<dim3(2 * D / 128, NTOK / 128), 128, SMEM_BIG>>>(
        p_cln, c_w1, c_b1, p_ch, nullptr, nullptr, NTOK, 2 * D, D, nullptr, nullptr);
    mma_gemm<64, 32, false, false, false, false><<<dim3(D / 128, NTOK / 64), 128, SMEM_SMALL>>>(
        p_ch, c_w2, c_b2, p_co, nullptr, nullptr, NTOK, D, 2 * D, nullptr, nullptr);
    // 12. out = LN(h + co)
    lnout_kernel<<<NTOK / 8, 256>>>(p_h, p_co, o_ln_g, o_ln_b, out);
}

// round 14
// speedup vs baseline: 1.2544x; 1.0129x over previous
#include <cuda_runtime.h>
#include <cstdint>
#include <math.h>

// ---------------- problem constants ----------------
#define NTOK 2048      // B*S
#define D    1024
#define H    4096
#define HE   4096
#define E    8
#define LN_EPS 1e-5f
#define NLB  (H / 128)   // 32 logit partial blocks

// ---------------- scratch (device globals) ----------------
__device__ float g_xhat [NTOK * D];
__device__ float g_r    [NTOK * D];
__device__ float g_lgp  [NTOK * NLB * E];
__device__ int   g_counts[E];
__device__ int   g_perm  [E * NTOK];
__device__ int   g_te   [NTOK * 2];
__device__ int   g_tp   [NTOK * 2];
__device__ float g_tg   [NTOK * 2];
__device__ float g_y    [2 * NTOK * D];
__device__ float g_f1   [2 * NTOK * HE];
__device__ float g_f2   [2 * NTOK * D];
__device__ float g_cln  [NTOK * D];
__device__ float g_ch   [NTOK * 2 * D];
__device__ float g_co   [NTOK * D];

// ---------------- helpers ----------------
__device__ __forceinline__ float gelu_f(float x) {
    return 0.5f * x * (1.0f + erff(x * 0.7071067811865475f));
}
__device__ __forceinline__ float to_tf32(float x) {
    uint32_t u;
    asm("cvt.rna.tf32.f32 %0, %1;" : "=r"(u) : "f"(x));
    return __uint_as_float(u);
}
__device__ __forceinline__ uint32_t smem_u32(const void* p) {
    uint32_t a;
    asm("{ .reg .u64 t; cvta.to.shared.u64 t, %1; cvt.u32.u64 %0, t; }" : "=r"(a) : "l"(p));
    return a;
}
__device__ __forceinline__ float warp_sum(float v) {
#pragma unroll
    for (int o = 16; o; o >>= 1) v += __shfl_xor_sync(0xffffffffu, v, o);
    return v;
}
// prefix base of expert e from counts (tiny; E=8)
__device__ __forceinline__ int base_of(const int* __restrict__ counts, int e) {
    int s = 0;
#pragma unroll
    for (int i = 0; i < E; i++) s += (i < e) ? counts[i] : 0;
    return s;
}

// cp.async (baseline PTX, compute_80+)
#define CP_ASYNC_CG(dst, src, srcsz) \
    asm volatile("cp.async.cg.shared.global [%0], [%1], 16, %2;" \
        :: "r"(dst), "l"(src), "r"(srcsz) : "memory")
#define CP_COMMIT() asm volatile("cp.async.commit_group;" ::: "memory")
#define CP_WAIT2()  asm volatile("cp.async.wait_group 2;" ::: "memory")

__device__ __forceinline__ void mma_tf32(float* c, const uint32_t* a, const uint32_t* b) {
    asm volatile(
        "mma.sync.aligned.m16n8k8.row.col.f32.tf32.tf32.f32 "
        "{%0,%1,%2,%3}, {%4,%5,%6,%7}, {%8,%9}, {%0,%1,%2,%3};"
        : "+f"(c[0]), "+f"(c[1]), "+f"(c[2]), "+f"(c[3])
        : "r"(a[0]), "r"(a[1]), "r"(a[2]), "r"(a[3]), "r"(b[0]), "r"(b[1]));
}

// ---------------- elementwise (warp-per-token) ----------------

// h = x + pos (NOT stored); LN -> xhat; r = tf32(xhat*g+b). Also zeroes counts.
__global__ void posln_kernel(const float* __restrict__ x,
                             const float* __restrict__ g, const float* __restrict__ b,
                             float* __restrict__ xhat, float* __restrict__ r,
                             int* __restrict__ counts) {
    if (blockIdx.x == 0 && threadIdx.x < E) counts[threadIdx.x] = 0;
    int wid = threadIdx.x >> 5, lane = threadIdx.x & 31;
    int t = blockIdx.x * 8 + wid;
    int sp = t & 1023;
    const float LOG1E4 = 9.210340371976184f;
    const float4* xr = (const float4*)(x + (size_t)t * D);
    float4 v[8];
    float s = 0.f;
#pragma unroll
    for (int j = 0; j < 8; j++) {
        int idx = j * 32 + lane;
        float4 val = xr[idx];
        int d0 = idx * 4;
        float a0 = (float)sp * expf(-LOG1E4 * (float)d0 * (1.f / (float)D));
        float a1 = (float)sp * expf(-LOG1E4 * (float)(d0 + 2) * (1.f / (float)D));
        float s0, c0, s1, c1;
        sincosf(a0, &s0, &c0);
        sincosf(a1, &s1, &c1);
        val.x += s0; val.y += c0;
        val.z += s1; val.w += c1;
        v[j] = val;
        s += val.x + val.y + val.z + val.w;
    }
    float mean = warp_sum(s) * (1.f / (float)D);
    float q = 0.f;
#pragma unroll
    for (int j = 0; j < 8; j++) {
        float dx = v[j].x - mean, dy = v[j].y - mean, dz = v[j].z - mean, dw = v[j].w - mean;
        q += dx * dx + dy * dy + dz * dz + dw * dw;
    }
    float rstd = rsqrtf(warp_sum(q) * (1.f / (float)D) + LN_EPS);
    float4* xh = (float4*)(xhat + (size_t)t * D);
    float4* rr = (float4*)(r + (size_t)t * D);
    const float4* g4 = (const float4*)g;
    const float4* b4 = (const float4*)b;
#pragma unroll
    for (int j = 0; j < 8; j++) {
        int idx = j * 32 + lane;
        float4 val = v[j];
        float4 xo;
        xo.x = (val.x - mean) * rstd; xo.y = (val.y - mean) * rstd;
        xo.z = (val.z - mean) * rstd; xo.w = (val.w - mean) * rstd;
        xh[idx] = xo;
        float4 gg = g4[idx], bb = b4[idx], ro;
        ro.x = to_tf32(xo.x * gg.x + bb.x); ro.y = to_tf32(xo.y * gg.y + bb.y);
        ro.z = to_tf32(xo.z * gg.z + bb.z); ro.w = to_tf32(xo.w * gg.w + bb.w);
        rr[idx] = ro;
    }
}

// out = LN((x + pos) + co) * g + b  (recomputes pos; identical expressions)
__global__ void lnout_kernel(const float* __restrict__ x, const float* __restrict__ X2,
                             const float* __restrict__ g, const float* __restrict__ b,
                             float* __restrict__ out) {
    int wid = threadIdx.x >> 5, lane = threadIdx.x & 31;
    int t = blockIdx.x * 8 + wid;
    int sp = t & 1023;
    const float LOG1E4 = 9.210340371976184f;
    const float4* xr = (const float4*)(x + (size_t)t * D);
    const float4* x2 = (const float4*)(X2 + (size_t)t * D);
    float4 v[8];
    float s = 0.f;
#pragma unroll
    for (int j = 0; j < 8; j++) {
        int idx = j * 32 + lane;
        float4 a = xr[idx], c = x2[idx];
        int d0 = idx * 4;
        float a0 = (float)sp * expf(-LOG1E4 * (float)d0 * (1.f / (float)D));
        float a1 = (float)sp * expf(-LOG1E4 * (float)(d0 + 2) * (1.f / (float)D));
        float s0, c0, s1, c1;
        sincosf(a0, &s0, &c0);
        sincosf(a1, &s1, &c1);
        a.x += s0 + c.x; a.y += c0 + c.y;
        a.z += s1 + c.z; a.w += c1 + c.w;
        v[j] = a;
        s += a.x + a.y + a.z + a.w;
    }
    float mean = warp_sum(s) * (1.f / (float)D);
    float q = 0.f;
#pragma unroll
    for (int j = 0; j < 8; j++) {
        float dx = v[j].x - mean, dy = v[j].y - mean, dz = v[j].z - mean, dw = v[j].w - mean;
        q += dx * dx + dy * dy + dz * dz + dw * dw;
    }
    float rstd = rsqrtf(warp_sum(q) * (1.f / (float)D) + LN_EPS);
    float4* o4 = (float4*)(out + (size_t)t * D);
    const float4* g4 = (const float4*)g;
    const float4* b4 = (const float4*)b;
#pragma unroll
    for (int j = 0; j < 8; j++) {
        int idx = j * 32 + lane;
        float4 gg = g4[idx], bb = b4[idx], o;
        o.x = (v[j].x - mean) * rstd * gg.x + bb.x;
        o.y = (v[j].y - mean) * rstd * gg.y + bb.y;
        o.z = (v[j].z - mean) * rstd * gg.z + bb.z;
        o.w = (v[j].w - mean) * rstd * gg.w + bb.w;
        o4[idx] = o;
    }
}

// combined = g1*f2[row1] + g2*f2[row2]; cln = tf32(LN(combined)*g+b)
__global__ void combine_ln_kernel(const float* __restrict__ f2, const int* __restrict__ counts,
                                  const int* __restrict__ te, const int* __restrict__ tp,
                                  const float* __restrict__ tg,
                                  const float* __restrict__ g, const float* __restrict__ b,
                                  float* __restrict__ cln) {
    __shared__ int sbase[E];
    if (threadIdx.x < E) sbase[threadIdx.x] = base_of(counts, threadIdx.x);
    __syncthreads();
    int wid = threadIdx.x >> 5, lane = threadIdx.x & 31;
    int t = blockIdx.x * 8 + wid;
    int e1 = te[2 * t], e2 = te[2 * t + 1];
    int p1 = tp[2 * t], p2 = tp[2 * t + 1];
    float g1 = tg[2 * t], g2 = tg[2 * t + 1];
    const float4* r1 = (const float4*)(f2 + (size_t)(sbase[e1] + p1) * D);
    const float4* r2 = (const float4*)(f2 + (size_t)(sbase[e2] + p2) * D);
    float4 v[8];
    float s = 0.f;
#pragma unroll
    for (int j = 0; j < 8; j++) {
        int idx = j * 32 + lane;
        float4 a = r1[idx], c = r2[idx], o;
        o.x = g1 * a.x + g2 * c.x; o.y = g1 * a.y + g2 * c.y;
        o.z = g1 * a.z + g2 * c.z; o.w = g1 * a.w + g2 * c.w;
        v[j] = o;
        s += o.x + o.y + o.z + o.w;
    }
    float mean = warp_sum(s) * (1.f / (float)D);
    float q = 0.f;
#pragma unroll
    for (int j = 0; j < 8; j++) {
        float dx = v[j].x - mean, dy = v[j].y - mean, dz = v[j].z - mean, dw = v[j].w - mean;
        q += dx * dx + dy * dy + dz * dz + dw * dw;
    }
    float rstd = rsqrtf(warp_sum(q) * (1.f / (float)D) + LN_EPS);
    float4* o4 = (float4*)(cln + (size_t)t * D);
    const float4* g4 = (const float4*)g;
    const float4* b4 = (const float4*)b;
#pragma unroll
    for (int j = 0; j < 8; j++) {
        int idx = j * 32 + lane;
        float4 gg = g4[idx], bb = b4[idx], o;
        o.x = to_tf32((v[j].x - mean) * rstd * gg.x + bb.x);
        o.y = to_tf32((v[j].y - mean) * rstd * gg.y + bb.y);
        o.z = to_tf32((v[j].z - mean) * rstd * gg.z + bb.z);
        o.w = to_tf32((v[j].w - mean) * rstd * gg.w + bb.w);
        o4[idx] = o;
    }
}

// gather: y[base(e)+i] = tf32(xhat[perm]*eg+eb)
__global__ void gather_kernel(const float* __restrict__ xhat, const float* __restrict__ elng,
                              const float* __restrict__ elnb, const int* __restrict__ counts,
                              const int* __restrict__ perm, float* __restrict__ y) {
    int wid = threadIdx.x >> 5, lane = threadIdx.x & 31;
    int e = blockIdx.y;
    int i = blockIdx.x * 8 + wid;
    if (i >= counts[e]) return;
    int base = base_of(counts, e);
    int t = perm[e * NTOK + i];
    const float4* src = (const float4*)(xhat + (size_t)t * D);
    const float4* g4 = (const float4*)(elng + (size_t)e * D);
    const float4* b4 = (const float4*)(elnb + (size_t)e * D);
    float4* dst = (float4*)(y + (size_t)(base + i) * D);
#pragma unroll
    for (int j = 0; j < 8; j++) {
        int idx = j * 32 + lane;
        float4 s = src[idx], gg = g4[idx], bb = b4[idx], o;
        o.x = to_tf32(s.x * gg.x + bb.x); o.y = to_tf32(s.y * gg.y + bb.y);
        o.z = to_tf32(s.z * gg.z + bb.z); o.w = to_tf32(s.w * gg.w + bb.w);
        dst[idx] = o;
    }
}

// router reduce: warp per token; lgp[t][32][8] coalesced; top2 by lane 0.
__global__ void router_top2_kernel(const float* __restrict__ lgp,
                                   const float* __restrict__ b2, const float* __restrict__ temp,
                                   int* __restrict__ counts, int* __restrict__ perm,
                                   int* __restrict__ te, int* __restrict__ tp,
                                   float* __restrict__ tg) {
    int wid = threadIdx.x >> 5, lane = threadIdx.x & 31;
    int t = blockIdx.x * 8 + wid;
    const float4* src = (const float4*)(lgp + (size_t)t * (NLB * E) + lane * 8);
    float4 va = src[0], vb = src[1];
    float v[E] = {va.x, va.y, va.z, va.w, vb.x, vb.y, vb.z, vb.w};
#pragma unroll
    for (int o = 16; o; o >>= 1)
#pragma unroll
        for (int e = 0; e < E; e++) v[e] += __shfl_xor_sync(0xffffffffu, v[e], o);
    if (lane == 0) {
        float invt = 1.0f / temp[0];
        float p[E];
        float mx = -1e30f;
#pragma unroll
        for (int e = 0; e < E; e++) { p[e] = (v[e] + b2[e]) * invt; mx = fmaxf(mx, p[e]); }
        float se = 0.f;
#pragma unroll
        for (int e = 0; e < E; e++) { p[e] = expf(p[e] - mx); se += p[e]; }
        float inv = 1.0f / se;
#pragma unroll
        for (int e = 0; e < E; e++) p[e] *= inv;
        int i1 = 0;
#pragma unroll
        for (int e = 1; e < E; e++) if (p[e] > p[i1]) i1 = e;
        int i2 = (i1 == 0) ? 1 : 0;
#pragma unroll
        for (int e = 0; e < E; e++) if (e != i1 && p[e] > p[i2]) i2 = e;
        int pos1 = atomicAdd(&counts[i1], 1);
        perm[i1 * NTOK + pos1] = t;
        int pos2 = atomicAdd(&counts[i2], 1);
        perm[i2 * NTOK + pos2] = t;
        te[2 * t] = i1; tp[2 * t] = pos1; tg[2 * t] = p[i1];
        te[2 * t + 1] = i2; tp[2 * t + 1] = pos2; tg[2 * t + 1] = p[i2];
    }
}

// ---------------- tf32 mma.sync GEMM (R10 core; compile-time K) -------------
// C[M,N] = act(A[M,K] @ B[K,N] + bias[N]); A K-contig, B N-contig.
// BM in {128,64}, BN=128, BK=16, 128 threads (4 warps), FIVE-stage cp.async.
// Issue-first ordering; 5 stages -> overwrite provably barrier-separated.
// LOGITS mode: skip C store, contract post-GELU tile with w2 -> lgp partials.
#define NSTG 5

template <int BM, int WN, int KT, bool DOGELU, bool ROUND, bool GROUPED, bool LOGITS>
__global__ void __launch_bounds__(128, (BM == 128) ? 2 : 3)
mma_gemm(const float* __restrict__ Abase, const float* __restrict__ Ball,
         const float* __restrict__ biasall, float* __restrict__ Cbase,
         const int* __restrict__ counts,
         int M_in, int N,
         const float* __restrict__ w2, float* __restrict__ lgp) {
    constexpr int K = KT;
    constexpr int NC = K / 16;
    constexpr int NT = WN / 8;
    constexpr int ACH = BM / 32;
    constexpr int ASTF = BM * 20;
    constexpr int STGF = ASTF + 16 * 136;
    constexpr int STGB = STGF * 4;

    int e = GROUPED ? blockIdx.z : 0;
    int M = GROUPED ? counts[e] : M_in;
    int m0 = blockIdx.y * BM;
    if (m0 >= M) return;
    int base = GROUPED ? base_of(counts, e) : 0;
    int n0 = blockIdx.x * 128;
    const float* A = Abase + (size_t)base * K;
    const float* B = GROUPED ? Ball + (size_t)e * (size_t)K * N : Ball;
    const float* bias = GROUPED ? biasall + (size_t)e * N : biasall;
    float* C = Cbase + (size_t)base * N;

    extern __shared__ float smf[];
    uint32_t sbase = smem_u32(smf);
    int tid = threadIdx.x;
    int wid = tid >> 5, lane = tid & 31;
    int gq = lane >> 2, qq = lane & 3;
    int m0w = (BM == 128) ? (wid & 1) * 64 : 0;
    int n0w = (BM == 128) ? (wid >> 1) * 64 : wid * 32;

    int aq = tid & 3, ar = tid >> 2;
    int bq = tid & 31, br = tid >> 5;
    uint32_t adst[ACH], bdst[4];
    const float* asrc[ACH];
    const float* bsrc[4];
    uint32_t asz[ACH];
#pragma unroll
    for (int i = 0; i < ACH; i++) {
        int r = ar + 32 * i;
        adst[i] = (uint32_t)(r * 80 + aq * 16);
        int row = m0 + r;
        asz[i] = (row < M) ? 16u : 0u;
        asrc[i] = A + (size_t)((row < M) ? row : 0) * K + aq * 4;
    }
#pragma unroll
    for (int i = 0; i < 4; i++) {
        int rb = br + 4 * i;
        bdst[i] = (uint32_t)(ASTF * 4 + rb * 544 + bq * 16);
        bsrc[i] = B + (size_t)rb * N + n0 + bq * 4;
    }

    float acc[4][NT][4];
#pragma unroll
    for (int i = 0; i < 4; i++)
#pragma unroll
        for (int j = 0; j < NT; j++)
#pragma unroll
            for (int l = 0; l < 4; l++) acc[i][j][l] = 0.f;

    // prologue: stages 0,1,2
#pragma unroll
    for (int pk = 0; pk < 3; pk++) {
        uint32_t sb = sbase + pk * STGB;
        int k0 = pk * 16;
#pragma unroll
        for (int i = 0; i < ACH; i++) CP_ASYNC_CG(sb + adst[i], asrc[i] + k0, asz[i]);
#pragma unroll
        for (int i = 0; i < 4; i++) CP_ASYNC_CG(sb + bdst[i], bsrc[i] + (size_t)k0 * N, 16u);
        CP_COMMIT();
    }
    CP_WAIT2();
    __syncthreads();

    uint32_t a0[4][4], b0[NT][2], a1[4][4], b1[NT][2];

#define LOADFRAG(AF, BF, ASP, BSP, KK)                                        \
    do {                                                                      \
        _Pragma("unroll")                                                     \
        for (int mt = 0; mt < 4; mt++) {                                      \
            int r = m0w + mt * 16 + gq;                                       \
            AF[mt][0] = __float_as_uint((ASP)[r * 20 + (KK) + qq]);           \
            AF[mt][1] = __float_as_uint((ASP)[(r + 8) * 20 + (KK) + qq]);     \
            AF[mt][2] = __float_as_uint((ASP)[r * 20 + (KK) + qq + 4]);       \
            AF[mt][3] = __float_as_uint((ASP)[(r + 8) * 20 + (KK) + qq + 4]); \
        }                                                                     \
        _Pragma("unroll")                                                     \
        for (int nt = 0; nt < NT; nt++) {                                     \
            int c = n0w + nt * 8 + gq;                                        \
            BF[nt][0] = __float_as_uint((BSP)[((KK) + qq) * 136 + c]);        \
            BF[nt][1] = __float_as_uint((BSP)[((KK) + qq + 4) * 136 + c]);    \
        }                                                                     \
    } while (0)

#define MMAALL(AF, BF)                                                        \
    do {                                                                      \
        _Pragma("unroll")                                                     \
        for (int mt = 0; mt < 4; mt++)                                        \
            _Pragma("unroll")                                                 \
            for (int nt = 0; nt < NT; nt++)                                   \
                mma_tf32(acc[mt][nt], AF[mt], BF[nt]);                        \
    } while (0)

    {
        const float* As0 = smf;
        const float* Bs0 = smf + ASTF;
        LOADFRAG(a0, b0, As0, Bs0, 0);
    }

#pragma unroll 5
    for (int kc = 0; kc < NC; kc++) {
        int sc = kc % NSTG;
        if (kc + 3 < NC) {
            int si = (kc + 3) % NSTG;
            uint32_t sb = sbase + si * STGB;
            int k0 = (kc + 3) * 16;
#pragma unroll
            for (int i = 0; i < ACH; i++) CP_ASYNC_CG(sb + adst[i], asrc[i] + k0, asz[i]);
#pragma unroll
            for (int i = 0; i < 4; i++) CP_ASYNC_CG(sb + bdst[i], bsrc[i] + (size_t)k0 * N, 16u);
        }
        CP_COMMIT();
        CP_WAIT2();
        __syncthreads();

        const float* Asc = smf + sc * STGF;
        const float* Bsc = Asc + ASTF;
        int sn = (kc + 1 < NC) ? ((kc + 1) % NSTG) : sc;
        const float* Asn = smf + sn * STGF;
        const float* Bsn = Asn + ASTF;

        LOADFRAG(a1, b1, Asc, Bsc, 8);
        MMAALL(a0, b0);
        LOADFRAG(a0, b0, Asn, Bsn, 0);
        MMAALL(a1, b1);
    }
#undef LOADFRAG
#undef MMAALL

    // ---------------- epilogue ----------------
    float* lgs = smf + NSTG * STGF;
    if (LOGITS) {
#pragma unroll
        for (int i = 0; i < 8; i++) lgs[i * 128 + tid] = 0.f;
        __syncthreads();
    }

#pragma unroll
    for (int mt = 0; mt < 4; mt++) {
        int row0 = m0 + m0w + mt * 16 + gq;
        int row1 = row0 + 8;
        float lg0[E], lg1[E];
        if (LOGITS) {
#pragma unroll
            for (int ee = 0; ee < E; ee++) { lg0[ee] = 0.f; lg1[ee] = 0.f; }
        }
#pragma unroll
        for (int nt = 0; nt < NT; nt++) {
            int col = n0 + n0w + nt * 8 + 2 * qq;
            float bb0 = bias[col], bb1 = bias[col + 1];
            float v0 = acc[mt][nt][0] + bb0;
            float v1 = acc[mt][nt][1] + bb1;
            float v2 = acc[mt][nt][2] + bb0;
            float v3 = acc[mt][nt][3] + bb1;
            if (DOGELU) { v0 = gelu_f(v0); v1 = gelu_f(v1); v2 = gelu_f(v2); v3 = gelu_f(v3); }
            if (LOGITS) {
                const float4* wr0 = (const float4*)(w2 + (size_t)col * E);
                float4 wa = wr0[0], wb = wr0[1];
                const float4* wr1 = (const float4*)(w2 + (size_t)(col + 1) * E);
                float4 wc = wr1[0], wd = wr1[1];
                lg0[0] += v0 * wa.x + v1 * wc.x; lg0[1] += v0 * wa.y + v1 * wc.y;
                lg0[2] += v0 * wa.z + v1 * wc.z; lg0[3] += v0 * wa.w + v1 * wc.w;
                lg0[4] += v0 * wb.x + v1 * wd.x; lg0[5] += v0 * wb.y + v1 * wd.y;
                lg0[6] += v0 * wb.z + v1 * wd.z; lg0[7] += v0 * wb.w + v1 * wd.w;
                lg1[0] += v2 * wa.x + v3 * wc.x; lg1[1] += v2 * wa.y + v3 * wc.y;
                lg1[2] += v2 * wa.z + v3 * wc.z; lg1[3] += v2 * wa.w + v3 * wc.w;
                lg1[4] += v2 * wb.x + v3 * wd.x; lg1[5] += v2 * wb.y + v3 * wd.y;
                lg1[6] += v2 * wb.z + v3 * wd.z; lg1[7] += v2 * wb.w + v3 * wd.w;
            } else {
                if (ROUND) { v0 = to_tf32(v0); v1 = to_tf32(v1); v2 = to_tf32(v2); v3 = to_tf32(v3); }
                if (row0 < M) *(float2*)(C + (size_t)row0 * N + col) = make_float2(v0, v1);
                if (row1 < M) *(float2*)(C + (size_t)row1 * N + col) = make_float2(v2, v3);
            }
        }
        if (LOGITS) {
#pragma unroll
            for (int off = 1; off <= 2; off <<= 1)
#pragma unroll
                for (int ee = 0; ee < E; ee++) {
                    lg0[ee] += __shfl_xor_sync(0xffffffffu, lg0[ee], off);
                    lg1[ee] += __shfl_xor_sync(0xffffffffu, lg1[ee], off);
                }
            if (qq == 0) {
                int r0 = m0w + mt * 16 + gq;
                int r1 = r0 + 8;
#pragma unroll
                for (int ee = 0; ee < E; ee++) {
                    atomicAdd(&lgs[r0 * E + ee], lg0[ee]);
                    atomicAdd(&lgs[r1 * E + ee], lg1[ee]);
                }
            }
        }
    }

    if (LOGITS) {
        __syncthreads();
        int row = tid;
        float4* dst = (float4*)(lgp + ((size_t)(m0 + row) * NLB + blockIdx.x) * E);
        const float4* src = (const float4*)&lgs[row * E];
        dst[0] = src[0];
        dst[1] = src[1];
    }
}

#define SMEM_BIG   (NSTG * (128 * 20 + 16 * 136) * 4)
#define SMEM_LOGIT (SMEM_BIG + 128 * E * 4)
#define SMEM_SMALL (NSTG * (64 * 20 + 16 * 136) * 4)

// ---------------- launch ----------------
extern "C" void kernel_launch(void* const* d_in, const int* in_sizes, int n_in,
                              void* d_out, int out_size) {
    const float* x      = (const float*)d_in[0];
    const float* r_ln_g = (const float*)d_in[1];
    const float* r_ln_b = (const float*)d_in[2];
    const float* r_w1   = (const float*)d_in[3];
    const float* r_b1   = (const float*)d_in[4];
    const float* r_w2   = (const float*)d_in[5];
    const float* r_b2   = (const float*)d_in[6];
    const float* temp   = (const float*)d_in[7];
    const float* e_ln_g = (const float*)d_in[8];
    const float* e_ln_b = (const float*)d_in[9];
    const float* e_w1   = (const float*)d_in[10];
    const float* e_b1   = (const float*)d_in[11];
    const float* e_w2   = (const float*)d_in[12];
    const float* e_b2   = (const float*)d_in[13];
    const float* c_ln_g = (const float*)d_in[14];
    const float* c_ln_b = (const float*)d_in[15];
    const float* c_w1   = (const float*)d_in[16];
    const float* c_b1   = (const float*)d_in[17];
    const float* c_w2   = (const float*)d_in[18];
    const float* c_b2   = (const float*)d_in[19];
    const float* o_ln_g = (const float*)d_in[20];
    const float* o_ln_b = (const float*)d_in[21];
    float* out = (float*)d_out;

    float *p_xhat, *p_r, *p_lgp, *p_tg, *p_y, *p_f1, *p_f2, *p_cln, *p_ch, *p_co;
    int *p_counts, *p_perm, *p_te, *p_tp;
    cudaGetSymbolAddress((void**)&p_xhat, g_xhat);
    cudaGetSymbolAddress((void**)&p_r, g_r);
    cudaGetSymbolAddress((void**)&p_lgp, g_lgp);
    cudaGetSymbolAddress((void**)&p_counts, g_counts);
    cudaGetSymbolAddress((void**)&p_perm, g_perm);
    cudaGetSymbolAddress((void**)&p_te, g_te);
    cudaGetSymbolAddress((void**)&p_tp, g_tp);
    cudaGetSymbolAddress((void**)&p_tg, g_tg);
    cudaGetSymbolAddress((void**)&p_y, g_y);
    cudaGetSymbolAddress((void**)&p_f1, g_f1);
    cudaGetSymbolAddress((void**)&p_f2, g_f2);
    cudaGetSymbolAddress((void**)&p_cln, g_cln);
    cudaGetSymbolAddress((void**)&p_ch, g_ch);
    cudaGetSymbolAddress((void**)&p_co, g_co);

    cudaFuncSetAttribute(mma_gemm<128, 64, D,      true,  false, false, true >, cudaFuncAttributeMaxDynamicSharedMemorySize, SMEM_LOGIT);
    cudaFuncSetAttribute(mma_gemm<128, 64, D,      true,  true,  true,  false>, cudaFuncAttributeMaxDynamicSharedMemorySize, SMEM_BIG);
    cudaFuncSetAttribute(mma_gemm<128, 64, HE,     false, false, true,  false>, cudaFuncAttributeMaxDynamicSharedMemorySize, SMEM_BIG);
    cudaFuncSetAttribute(mma_gemm<128, 64, D,      true,  true,  false, false>, cudaFuncAttributeMaxDynamicSharedMemorySize, SMEM_BIG);
    cudaFuncSetAttribute(mma_gemm<64,  32, 2 * D,  false, false, false, false>, cudaFuncAttributeMaxDynamicSharedMemorySize, SMEM_SMALL);

    // 1. h = x + pos (transient); LN -> xhat; router input r; zero counts
    posln_kernel<<<NTOK / 8, 256>>>(x, r_ln_g, r_ln_b, p_xhat, p_r, p_counts);
    // 2. router GEMM1 with FUSED logit partials (no rh materialization)
    mma_gemm<128, 64, D, true, false, false, true><<<dim3(H / 128, NTOK / 128), 128, SMEM_LOGIT>>>(
        p_r, r_w1, r_b1, nullptr, nullptr, NTOK, H, r_w2, p_lgp);
    // 3. reduce partials -> softmax -> top2 -> compaction
    router_top2_kernel<<<NTOK / 8, 256>>>(p_lgp, r_b2, temp, p_counts, p_perm, p_te, p_tp, p_tg);
    // 4. gather expert inputs (per-expert LN affine, tf32); bases inline
    gather_kernel<<<dim3(NTOK / 8, E), 256>>>(p_xhat, e_ln_g, e_ln_b, p_counts, p_perm, p_y);
    // 5. expert FFN layer 1
    mma_gemm<128, 64, D, true, true, true, false><<<dim3(HE / 128, NTOK / 128, E), 128, SMEM_BIG>>>(
        p_y, e_w1, e_b1, p_f1, p_counts, 0, HE, nullptr, nullptr);
    // 6. expert FFN layer 2
    mma_gemm<128, 64, HE, false, false, true, false><<<dim3(D / 128, NTOK / 128, E), 128, SMEM_BIG>>>(
        p_f1, e_w2, e_b2, p_f2, p_counts, 0, D, nullptr, nullptr);
    // 7. combine (gates) + combiner LN fused; bases inline
    combine_ln_kernel<<<NTOK / 8, 256>>>(p_f2, p_counts, p_te, p_tp, p_tg, c_ln_g, c_ln_b, p_cln);
    // 8. combiner MLP
    mma_gemm<128, 64, D, true, true, false, false><<<dim3(2 * D / 128, NTOK / 128), 128, SMEM_BIG>>>(
        p_cln, c_w1, c_b1, p_ch, nullptr, NTOK, 2 * D, nullptr, nullptr);
    mma_gemm<64, 32, 2 * D, false, false, false, false><<<dim3(D / 128, NTOK / 64), 128, SMEM_SMALL>>>(
        p_ch, c_w2, c_b2, p_co, nullptr, NTOK, D, nullptr, nullptr);
    // 9. out = LN((x+pos) + co)  (pos recomputed; h never stored)
    lnout_kernel<<<NTOK / 8, 256>>>(x, p_co, o_ln_g, o_ln_b, out);
}

// round 16
// speedup vs baseline: 1.2846x; 1.0240x over previous
#include <cuda_runtime.h>
#include <cstdint>
#include <math.h>

// ---------------- problem constants ----------------
#define NTOK 2048      // B*S
#define D    1024
#define H    4096
#define HE   4096
#define E    8
#define LN_EPS 1e-5f
#define NLB  (H / 128)   // 32 logit partial blocks

// ---------------- scratch (device globals) ----------------
__device__ float g_xhat [NTOK * D];
__device__ float g_r    [NTOK * D];
__device__ float g_lgp  [NTOK * NLB * E];
__device__ int   g_counts[E];
__device__ int   g_perm  [E * NTOK];
__device__ int   g_te   [NTOK * 2];
__device__ int   g_tp   [NTOK * 2];
__device__ float g_tg   [NTOK * 2];
__device__ float g_y    [2 * NTOK * D];
__device__ float g_f1   [2 * NTOK * HE];
__device__ float g_f2   [2 * NTOK * D];
__device__ float g_cln  [NTOK * D];
__device__ float g_ch   [NTOK * 2 * D];
__device__ float g_co   [NTOK * D];

// ---------------- helpers ----------------
__device__ __forceinline__ float gelu_f(float x) {
    return 0.5f * x * (1.0f + erff(x * 0.7071067811865475f));
}
__device__ __forceinline__ float to_tf32(float x) {
    uint32_t u;
    asm("cvt.rna.tf32.f32 %0, %1;" : "=r"(u) : "f"(x));
    return __uint_as_float(u);
}
__device__ __forceinline__ uint32_t smem_u32(const void* p) {
    uint32_t a;
    asm("{ .reg .u64 t; cvta.to.shared.u64 t, %1; cvt.u32.u64 %0, t; }" : "=r"(a) : "l"(p));
    return a;
}
__device__ __forceinline__ float warp_sum(float v) {
#pragma unroll
    for (int o = 16; o; o >>= 1) v += __shfl_xor_sync(0xffffffffu, v, o);
    return v;
}
// prefix base of expert e from counts (tiny; E=8)
__device__ __forceinline__ int base_of(const int* __restrict__ counts, int e) {
    int s = 0;
#pragma unroll
    for (int i = 0; i < E; i++) s += (i < e) ? counts[i] : 0;
    return s;
}

// cp.async (baseline PTX, compute_80+)
#define CP_ASYNC_CG(dst, src, srcsz) \
    asm volatile("cp.async.cg.shared.global [%0], [%1], 16, %2;" \
        :: "r"(dst), "l"(src), "r"(srcsz) : "memory")
#define CP_COMMIT() asm volatile("cp.async.commit_group;" ::: "memory")
#define CP_WAIT2()  asm volatile("cp.async.wait_group 2;" ::: "memory")

__device__ __forceinline__ void mma_tf32(float* c, const uint32_t* a, const uint32_t* b) {
    asm volatile(
        "mma.sync.aligned.m16n8k8.row.col.f32.tf32.tf32.f32 "
        "{%0,%1,%2,%3}, {%4,%5,%6,%7}, {%8,%9}, {%0,%1,%2,%3};"
        : "+f"(c[0]), "+f"(c[1]), "+f"(c[2]), "+f"(c[3])
        : "r"(a[0]), "r"(a[1]), "r"(a[2]), "r"(a[3]), "r"(b[0]), "r"(b[1]));
}

// ---------------- elementwise (warp-per-token) ----------------

// h = x + pos (NOT stored); LN -> xhat; r = tf32(xhat*g+b). Also zeroes counts.
__global__ void posln_kernel(const float* __restrict__ x,
                             const float* __restrict__ g, const float* __restrict__ b,
                             float* __restrict__ xhat, float* __restrict__ r,
                             int* __restrict__ counts) {
    if (blockIdx.x == 0 && threadIdx.x < E) counts[threadIdx.x] = 0;
    int wid = threadIdx.x >> 5, lane = threadIdx.x & 31;
    int t = blockIdx.x * 8 + wid;
    int sp = t & 1023;
    const float LOG1E4 = 9.210340371976184f;
    const float4* xr = (const float4*)(x + (size_t)t * D);
    float4 v[8];
    float s = 0.f;
#pragma unroll
    for (int j = 0; j < 8; j++) {
        int idx = j * 32 + lane;
        float4 val = xr[idx];
        int d0 = idx * 4;
        float a0 = (float)sp * expf(-LOG1E4 * (float)d0 * (1.f / (float)D));
        float a1 = (float)sp * expf(-LOG1E4 * (float)(d0 + 2) * (1.f / (float)D));
        float s0, c0, s1, c1;
        sincosf(a0, &s0, &c0);
        sincosf(a1, &s1, &c1);
        val.x += s0; val.y += c0;
        val.z += s1; val.w += c1;
        v[j] = val;
        s += val.x + val.y + val.z + val.w;
    }
    float mean = warp_sum(s) * (1.f / (float)D);
    float q = 0.f;
#pragma unroll
    for (int j = 0; j < 8; j++) {
        float dx = v[j].x - mean, dy = v[j].y - mean, dz = v[j].z - mean, dw = v[j].w - mean;
        q += dx * dx + dy * dy + dz * dz + dw * dw;
    }
    float rstd = rsqrtf(warp_sum(q) * (1.f / (float)D) + LN_EPS);
    float4* xh = (float4*)(xhat + (size_t)t * D);
    float4* rr = (float4*)(r + (size_t)t * D);
    const float4* g4 = (const float4*)g;
    const float4* b4 = (const float4*)b;
#pragma unroll
    for (int j = 0; j < 8; j++) {
        int idx = j * 32 + lane;
        float4 val = v[j];
        float4 xo;
        xo.x = (val.x - mean) * rstd; xo.y = (val.y - mean) * rstd;
        xo.z = (val.z - mean) * rstd; xo.w = (val.w - mean) * rstd;
        xh[idx] = xo;
        float4 gg = g4[idx], bb = b4[idx], ro;
        ro.x = to_tf32(xo.x * gg.x + bb.x); ro.y = to_tf32(xo.y * gg.y + bb.y);
        ro.z = to_tf32(xo.z * gg.z + bb.z); ro.w = to_tf32(xo.w * gg.w + bb.w);
        rr[idx] = ro;
    }
}

// out = LN((x + pos) + co) * g + b  (recomputes pos; identical expressions)
__global__ void lnout_kernel(const float* __restrict__ x, const float* __restrict__ X2,
                             const float* __restrict__ g, const float* __restrict__ b,
                             float* __restrict__ out) {
    int wid = threadIdx.x >> 5, lane = threadIdx.x & 31;
    int t = blockIdx.x * 8 + wid;
    int sp = t & 1023;
    const float LOG1E4 = 9.210340371976184f;
    const float4* xr = (const float4*)(x + (size_t)t * D);
    const float4* x2 = (const float4*)(X2 + (size_t)t * D);
    float4 v[8];
    float s = 0.f;
#pragma unroll
    for (int j = 0; j < 8; j++) {
        int idx = j * 32 + lane;
        float4 a = xr[idx], c = x2[idx];
        int d0 = idx * 4;
        float a0 = (float)sp * expf(-LOG1E4 * (float)d0 * (1.f / (float)D));
        float a1 = (float)sp * expf(-LOG1E4 * (float)(d0 + 2) * (1.f / (float)D));
        float s0, c0, s1, c1;
        sincosf(a0, &s0, &c0);
        sincosf(a1, &s1, &c1);
        a.x += s0 + c.x; a.y += c0 + c.y;
        a.z += s1 + c.z; a.w += c1 + c.w;
        v[j] = a;
        s += a.x + a.y + a.z + a.w;
    }
    float mean = warp_sum(s) * (1.f / (float)D);
    float q = 0.f;
#pragma unroll
    for (int j = 0; j < 8; j++) {
        float dx = v[j].x - mean, dy = v[j].y - mean, dz = v[j].z - mean, dw = v[j].w - mean;
        q += dx * dx + dy * dy + dz * dz + dw * dw;
    }
    float rstd = rsqrtf(warp_sum(q) * (1.f / (float)D) + LN_EPS);
    float4* o4 = (float4*)(out + (size_t)t * D);
    const float4* g4 = (const float4*)g;
    const float4* b4 = (const float4*)b;
#pragma unroll
    for (int j = 0; j < 8; j++) {
        int idx = j * 32 + lane;
        float4 gg = g4[idx], bb = b4[idx], o;
        o.x = (v[j].x - mean) * rstd * gg.x + bb.x;
        o.y = (v[j].y - mean) * rstd * gg.y + bb.y;
        o.z = (v[j].z - mean) * rstd * gg.z + bb.z;
        o.w = (v[j].w - mean) * rstd * gg.w + bb.w;
        o4[idx] = o;
    }
}

// combined = g1*f2[row1] + g2*f2[row2]; cln = tf32(LN(combined)*g+b)
__global__ void combine_ln_kernel(const float* __restrict__ f2, const int* __restrict__ counts,
                                  const int* __restrict__ te, const int* __restrict__ tp,
                                  const float* __restrict__ tg,
                                  const float* __restrict__ g, const float* __restrict__ b,
                                  float* __restrict__ cln) {
    __shared__ int sbase[E];
    if (threadIdx.x < E) sbase[threadIdx.x] = base_of(counts, threadIdx.x);
    __syncthreads();
    int wid = threadIdx.x >> 5, lane = threadIdx.x & 31;
    int t = blockIdx.x * 8 + wid;
    int e1 = te[2 * t], e2 = te[2 * t + 1];
    int p1 = tp[2 * t], p2 = tp[2 * t + 1];
    float g1 = tg[2 * t], g2 = tg[2 * t + 1];
    const float4* r1 = (const float4*)(f2 + (size_t)(sbase[e1] + p1) * D);
    const float4* r2 = (const float4*)(f2 + (size_t)(sbase[e2] + p2) * D);
    float4 v[8];
    float s = 0.f;
#pragma unroll
    for (int j = 0; j < 8; j++) {
        int idx = j * 32 + lane;
        float4 a = r1[idx], c = r2[idx], o;
        o.x = g1 * a.x + g2 * c.x; o.y = g1 * a.y + g2 * c.y;
        o.z = g1 * a.z + g2 * c.z; o.w = g1 * a.w + g2 * c.w;
        v[j] = o;
        s += o.x + o.y + o.z + o.w;
    }
    float mean = warp_sum(s) * (1.f / (float)D);
    float q = 0.f;
#pragma unroll
    for (int j = 0; j < 8; j++) {
        float dx = v[j].x - mean, dy = v[j].y - mean, dz = v[j].z - mean, dw = v[j].w - mean;
        q += dx * dx + dy * dy + dz * dz + dw * dw;
    }
    float rstd = rsqrtf(warp_sum(q) * (1.f / (float)D) + LN_EPS);
    float4* o4 = (float4*)(cln + (size_t)t * D);
    const float4* g4 = (const float4*)g;
    const float4* b4 = (const float4*)b;
#pragma unroll
    for (int j = 0; j < 8; j++) {
        int idx = j * 32 + lane;
        float4 gg = g4[idx], bb = b4[idx], o;
        o.x = to_tf32((v[j].x - mean) * rstd * gg.x + bb.x);
        o.y = to_tf32((v[j].y - mean) * rstd * gg.y + bb.y);
        o.z = to_tf32((v[j].z - mean) * rstd * gg.z + bb.z);
        o.w = to_tf32((v[j].w - mean) * rstd * gg.w + bb.w);
        o4[idx] = o;
    }
}

// gather: y[base(e)+i] = tf32(xhat[perm]*eg+eb)
__global__ void gather_kernel(const float* __restrict__ xhat, const float* __restrict__ elng,
                              const float* __restrict__ elnb, const int* __restrict__ counts,
                              const int* __restrict__ perm, float* __restrict__ y) {
    int wid = threadIdx.x >> 5, lane = threadIdx.x & 31;
    int e = blockIdx.y;
    int i = blockIdx.x * 8 + wid;
    if (i >= counts[e]) return;
    int base = base_of(counts, e);
    int t = perm[e * NTOK + i];
    const float4* src = (const float4*)(xhat + (size_t)t * D);
    const float4* g4 = (const float4*)(elng + (size_t)e * D);
    const float4* b4 = (const float4*)(elnb + (size_t)e * D);
    float4* dst = (float4*)(y + (size_t)(base + i) * D);
#pragma unroll
    for (int j = 0; j < 8; j++) {
        int idx = j * 32 + lane;
        float4 s = src[idx], gg = g4[idx], bb = b4[idx], o;
        o.x = to_tf32(s.x * gg.x + bb.x); o.y = to_tf32(s.y * gg.y + bb.y);
        o.z = to_tf32(s.z * gg.z + bb.z); o.w = to_tf32(s.w * gg.w + bb.w);
        dst[idx] = o;
    }
}

// router reduce: warp per token; lgp[t][32][8] coalesced; top2 by lane 0.
__global__ void router_top2_kernel(const float* __restrict__ lgp,
                                   const float* __restrict__ b2, const float* __restrict__ temp,
                                   int* __restrict__ counts, int* __restrict__ perm,
                                   int* __restrict__ te, int* __restrict__ tp,
                                   float* __restrict__ tg) {
    int wid = threadIdx.x >> 5, lane = threadIdx.x & 31;
    int t = blockIdx.x * 8 + wid;
    const float4* src = (const float4*)(lgp + (size_t)t * (NLB * E) + lane * 8);
    float4 va = src[0], vb = src[1];
    float v[E] = {va.x, va.y, va.z, va.w, vb.x, vb.y, vb.z, vb.w};
#pragma unroll
    for (int o = 16; o; o >>= 1)
#pragma unroll
        for (int e = 0; e < E; e++) v[e] += __shfl_xor_sync(0xffffffffu, v[e], o);
    if (lane == 0) {
        float invt = 1.0f / temp[0];
        float p[E];
        float mx = -1e30f;
#pragma unroll
        for (int e = 0; e < E; e++) { p[e] = (v[e] + b2[e]) * invt; mx = fmaxf(mx, p[e]); }
        float se = 0.f;
#pragma unroll
        for (int e = 0; e < E; e++) { p[e] = expf(p[e] - mx); se += p[e]; }
        float inv = 1.0f / se;
#pragma unroll
        for (int e = 0; e < E; e++) p[e] *= inv;
        int i1 = 0;
#pragma unroll
        for (int e = 1; e < E; e++) if (p[e] > p[i1]) i1 = e;
        int i2 = (i1 == 0) ? 1 : 0;
#pragma unroll
        for (int e = 0; e < E; e++) if (e != i1 && p[e] > p[i2]) i2 = e;
        int pos1 = atomicAdd(&counts[i1], 1);
        perm[i1 * NTOK + pos1] = t;
        int pos2 = atomicAdd(&counts[i2], 1);
        perm[i2 * NTOK + pos2] = t;
        te[2 * t] = i1; tp[2 * t] = pos1; tg[2 * t] = p[i1];
        te[2 * t + 1] = i2; tp[2 * t + 1] = pos2; tg[2 * t + 1] = p[i2];
    }
}

// ---------------- tf32 mma.sync GEMM (R14 core; split main/tail loop) -------
// C[M,N] = act(A[M,K] @ B[K,N] + bias[N]); A K-contig, B N-contig.
// BM in {128,64}, BN=128, BK=16, 128 threads (4 warps), FIVE-stage cp.async.
// Issue-first single-stage schedule (SAFE: issue at kc targets slot of stage
// kc-2, whose last reads were at iteration kc-2, separated by barrier kc-1).
// Main loop (issue unconditional) + 3-iteration tail (no issue).
// LOGITS mode: skip C store, contract post-GELU tile with w2 -> lgp partials.
#define NSTG 5

template <int BM, int WN, int KT, bool DOGELU, bool ROUND, bool GROUPED, bool LOGITS>
__global__ void __launch_bounds__(128, (BM == 128) ? 2 : 3)
mma_gemm(const float* __restrict__ Abase, const float* __restrict__ Ball,
         const float* __restrict__ biasall, float* __restrict__ Cbase,
         const int* __restrict__ counts,
         int M_in, int N,
         const float* __restrict__ w2, float* __restrict__ lgp) {
    constexpr int K = KT;
    constexpr int NC = K / 16;
    constexpr int NT = WN / 8;
    constexpr int ACH = BM / 32;
    constexpr int ASTF = BM * 20;
    constexpr int STGF = ASTF + 16 * 136;
    constexpr int STGB = STGF * 4;

    int e = GROUPED ? blockIdx.z : 0;
    int M = GROUPED ? counts[e] : M_in;
    int m0 = blockIdx.y * BM;
    if (m0 >= M) return;
    int base = GROUPED ? base_of(counts, e) : 0;
    int n0 = blockIdx.x * 128;
    const float* A = Abase + (size_t)base * K;
    const float* B = GROUPED ? Ball + (size_t)e * (size_t)K * N : Ball;
    const float* bias = GROUPED ? biasall + (size_t)e * N : biasall;
    float* C = Cbase + (size_t)base * N;

    extern __shared__ float smf[];
    uint32_t sbase = smem_u32(smf);
    int tid = threadIdx.x;
    int wid = tid >> 5, lane = tid & 31;
    int gq = lane >> 2, qq = lane & 3;
    int m0w = (BM == 128) ? (wid & 1) * 64 : 0;
    int n0w = (BM == 128) ? (wid >> 1) * 64 : wid * 32;

    int aq = tid & 3, ar = tid >> 2;
    int bq = tid & 31, br = tid >> 5;
    uint32_t adst[ACH], bdst[4];
    const float* asrc[ACH];
    const float* bsrc[4];
    uint32_t asz[ACH];
#pragma unroll
    for (int i = 0; i < ACH; i++) {
        int r = ar + 32 * i;
        adst[i] = (uint32_t)(r * 80 + aq * 16);
        int row = m0 + r;
        asz[i] = (row < M) ? 16u : 0u;
        asrc[i] = A + (size_t)((row < M) ? row : 0) * K + aq * 4;
    }
#pragma unroll
    for (int i = 0; i < 4; i++) {
        int rb = br + 4 * i;
        bdst[i] = (uint32_t)(ASTF * 4 + rb * 544 + bq * 16);
        bsrc[i] = B + (size_t)rb * N + n0 + bq * 4;
    }

    float acc[4][NT][4];
#pragma unroll
    for (int i = 0; i < 4; i++)
#pragma unroll
        for (int j = 0; j < NT; j++)
#pragma unroll
            for (int l = 0; l < 4; l++) acc[i][j][l] = 0.f;

#define ISSUE_STAGE(ST)                                                       \
    do {                                                                      \
        uint32_t sb = sbase + ((ST) % NSTG) * STGB;                           \
        int k0 = (ST) * 16;                                                   \
        _Pragma("unroll")                                                     \
        for (int i = 0; i < ACH; i++) CP_ASYNC_CG(sb + adst[i], asrc[i] + k0, asz[i]); \
        _Pragma("unroll")                                                     \
        for (int i = 0; i < 4; i++) CP_ASYNC_CG(sb + bdst[i], bsrc[i] + (size_t)k0 * N, 16u); \
    } while (0)

    // prologue: stages 0,1,2 as three groups
#pragma unroll
    for (int pk = 0; pk < 3; pk++) { ISSUE_STAGE(pk); CP_COMMIT(); }
    CP_WAIT2();            // stage 0 resident
    __syncthreads();

    uint32_t a0[4][4], b0[NT][2], a1[4][4], b1[NT][2];

#define LOADFRAG(AF, BF, ASP, BSP, KK)                                        \
    do {                                                                      \
        _Pragma("unroll")                                                     \
        for (int mt = 0; mt < 4; mt++) {                                      \
            int r = m0w + mt * 16 + gq;                                       \
            AF[mt][0] = __float_as_uint((ASP)[r * 20 + (KK) + qq]);           \
            AF[mt][1] = __float_as_uint((ASP)[(r + 8) * 20 + (KK) + qq]);     \
            AF[mt][2] = __float_as_uint((ASP)[r * 20 + (KK) + qq + 4]);       \
            AF[mt][3] = __float_as_uint((ASP)[(r + 8) * 20 + (KK) + qq + 4]); \
        }                                                                     \
        _Pragma("unroll")                                                     \
        for (int nt = 0; nt < NT; nt++) {                                     \
            int c = n0w + nt * 8 + gq;                                        \
            BF[nt][0] = __float_as_uint((BSP)[((KK) + qq) * 136 + c]);        \
            BF[nt][1] = __float_as_uint((BSP)[((KK) + qq + 4) * 136 + c]);    \
        }                                                                     \
    } while (0)

#define MMAALL(AF, BF)                                                        \
    do {                                                                      \
        _Pragma("unroll")                                                     \
        for (int mt = 0; mt < 4; mt++)                                        \
            _Pragma("unroll")                                                 \
            for (int nt = 0; nt < NT; nt++)                                   \
                mma_tf32(acc[mt][nt], AF[mt], BF[nt]);                        \
    } while (0)

#define KBODY(KC)                                                             \
    do {                                                                      \
        CP_COMMIT();                                                          \
        CP_WAIT2();                                                           \
        __syncthreads();                                                      \
        const float* Asc = smf + ((KC) % NSTG) * STGF;                        \
        const float* Bsc = Asc + ASTF;                                        \
        int snn = ((KC) + 1 < NC) ? (((KC) + 1) % NSTG) : ((KC) % NSTG);      \
        const float* Asn = smf + snn * STGF;                                  \
        const float* Bsn = Asn + ASTF;                                        \
        LOADFRAG(a1, b1, Asc, Bsc, 8);                                        \
        MMAALL(a0, b0);                                                       \
        LOADFRAG(a0, b0, Asn, Bsn, 0);                                        \
        MMAALL(a1, b1);                                                       \
    } while (0)

    {
        const float* As0 = smf;
        const float* Bs0 = smf + ASTF;
        LOADFRAG(a0, b0, As0, Bs0, 0);
    }

    // main loop: issue always valid (kc + 3 <= NC - 1)
#pragma unroll 5
    for (int kc = 0; kc < NC - 3; kc++) {
        ISSUE_STAGE(kc + 3);
        KBODY(kc);
    }
    // tail: last 3 iterations, no issue
#pragma unroll
    for (int kc = NC - 3; kc < NC; kc++) {
        KBODY(kc);
    }
#undef KBODY
#undef LOADFRAG
#undef MMAALL
#undef ISSUE_STAGE

    // ---------------- epilogue ----------------
    float* lgs = smf + NSTG * STGF;
    if (LOGITS) {
#pragma unroll
        for (int i = 0; i < 8; i++) lgs[i * 128 + tid] = 0.f;
        __syncthreads();
    }

#pragma unroll
    for (int mt = 0; mt < 4; mt++) {
        int row0 = m0 + m0w + mt * 16 + gq;
        int row1 = row0 + 8;
        float lg0[E], lg1[E];
        if (LOGITS) {
#pragma unroll
            for (int ee = 0; ee < E; ee++) { lg0[ee] = 0.f; lg1[ee] = 0.f; }
        }
#pragma unroll
        for (int nt = 0; nt < NT; nt++) {
            int col = n0 + n0w + nt * 8 + 2 * qq;
            float bb0 = bias[col], bb1 = bias[col + 1];
            float v0 = acc[mt][nt][0] + bb0;
            float v1 = acc[mt][nt][1] + bb1;
            float v2 = acc[mt][nt][2] + bb0;
            float v3 = acc[mt][nt][3] + bb1;
            if (DOGELU) { v0 = gelu_f(v0); v1 = gelu_f(v1); v2 = gelu_f(v2); v3 = gelu_f(v3); }
            if (LOGITS) {
                const float4* wr0 = (const float4*)(w2 + (size_t)col * E);
                float4 wa = wr0[0], wb = wr0[1];
                const float4* wr1 = (const float4*)(w2 + (size_t)(col + 1) * E);
                float4 wc = wr1[0], wd = wr1[1];
                lg0[0] += v0 * wa.x + v1 * wc.x; lg0[1] += v0 * wa.y + v1 * wc.y;
                lg0[2] += v0 * wa.z + v1 * wc.z; lg0[3] += v0 * wa.w + v1 * wc.w;
                lg0[4] += v0 * wb.x + v1 * wd.x; lg0[5] += v0 * wb.y + v1 * wd.y;
                lg0[6] += v0 * wb.z + v1 * wd.z; lg0[7] += v0 * wb.w + v1 * wd.w;
                lg1[0] += v2 * wa.x + v3 * wc.x; lg1[1] += v2 * wa.y + v3 * wc.y;
                lg1[2] += v2 * wa.z + v3 * wc.z; lg1[3] += v2 * wa.w + v3 * wc.w;
                lg1[4] += v2 * wb.x + v3 * wd.x; lg1[5] += v2 * wb.y + v3 * wd.y;
                lg1[6] += v2 * wb.z + v3 * wd.z; lg1[7] += v2 * wb.w + v3 * wd.w;
            } else {
                if (ROUND) { v0 = to_tf32(v0); v1 = to_tf32(v1); v2 = to_tf32(v2); v3 = to_tf32(v3); }
                if (row0 < M) *(float2*)(C + (size_t)row0 * N + col) = make_float2(v0, v1);
                if (row1 < M) *(float2*)(C + (size_t)row1 * N + col) = make_float2(v2, v3);
            }
        }
        if (LOGITS) {
#pragma unroll
            for (int off = 1; off <= 2; off <<= 1)
#pragma unroll
                for (int ee = 0; ee < E; ee++) {
                    lg0[ee] += __shfl_xor_sync(0xffffffffu, lg0[ee], off);
                    lg1[ee] += __shfl_xor_sync(0xffffffffu, lg1[ee], off);
                }
            if (qq == 0) {
                int r0 = m0w + mt * 16 + gq;
                int r1 = r0 + 8;
#pragma unroll
                for (int ee = 0; ee < E; ee++) {
                    atomicAdd(&lgs[r0 * E + ee], lg0[ee]);   // exactly 2 adds/cell
                    atomicAdd(&lgs[r1 * E + ee], lg1[ee]);   // -> deterministic
                }
            }
        }
    }

    if (LOGITS) {
        __syncthreads();
        int row = tid;
        float4* dst = (float4*)(lgp + ((size_t)(m0 + row) * NLB + blockIdx.x) * E);
        const float4* src = (const float4*)&lgs[row * E];
        dst[0] = src[0];
        dst[1] = src[1];
    }
}

#define SMEM_BIG   (NSTG * (128 * 20 + 16 * 136) * 4)
#define SMEM_LOGIT (SMEM_BIG + 128 * E * 4)
#define SMEM_SMALL (NSTG * (64 * 20 + 16 * 136) * 4)

// ---------------- launch ----------------
extern "C" void kernel_launch(void* const* d_in, const int* in_sizes, int n_in,
                              void* d_out, int out_size) {
    const float* x      = (const float*)d_in[0];
    const float* r_ln_g = (const float*)d_in[1];
    const float* r_ln_b = (const float*)d_in[2];
    const float* r_w1   = (const float*)d_in[3];
    const float* r_b1   = (const float*)d_in[4];
    const float* r_w2   = (const float*)d_in[5];
    const float* r_b2   = (const float*)d_in[6];
    const float* temp   = (const float*)d_in[7];
    const float* e_ln_g = (const float*)d_in[8];
    const float* e_ln_b = (const float*)d_in[9];
    const float* e_w1   = (const float*)d_in[10];
    const float* e_b1   = (const float*)d_in[11];
    const float* e_w2   = (const float*)d_in[12];
    const float* e_b2   = (const float*)d_in[13];
    const float* c_ln_g = (const float*)d_in[14];
    const float* c_ln_b = (const float*)d_in[15];
    const float* c_w1   = (const float*)d_in[16];
    const float* c_b1   = (const float*)d_in[17];
    const float* c_w2   = (const float*)d_in[18];
    const float* c_b2   = (const float*)d_in[19];
    const float* o_ln_g = (const float*)d_in[20];
    const float* o_ln_b = (const float*)d_in[21];
    float* out = (float*)d_out;

    float *p_xhat, *p_r, *p_lgp, *p_tg, *p_y, *p_f1, *p_f2, *p_cln, *p_ch, *p_co;
    int *p_counts, *p_perm, *p_te, *p_tp;
    cudaGetSymbolAddress((void**)&p_xhat, g_xhat);
    cudaGetSymbolAddress((void**)&p_r, g_r);
    cudaGetSymbolAddress((void**)&p_lgp, g_lgp);
    cudaGetSymbolAddress((void**)&p_counts, g_counts);
    cudaGetSymbolAddress((void**)&p_perm, g_perm);
    cudaGetSymbolAddress((void**)&p_te, g_te);
    cudaGetSymbolAddress((void**)&p_tp, g_tp);
    cudaGetSymbolAddress((void**)&p_tg, g_tg);
    cudaGetSymbolAddress((void**)&p_y, g_y);
    cudaGetSymbolAddress((void**)&p_f1, g_f1);
    cudaGetSymbolAddress((void**)&p_f2, g_f2);
    cudaGetSymbolAddress((void**)&p_cln, g_cln);
    cudaGetSymbolAddress((void**)&p_ch, g_ch);
    cudaGetSymbolAddress((void**)&p_co, g_co);

    cudaFuncSetAttribute(mma_gemm<128, 64, D,      true,  false, false, true >, cudaFuncAttributeMaxDynamicSharedMemorySize, SMEM_LOGIT);
    cudaFuncSetAttribute(mma_gemm<128, 64, D,      true,  true,  true,  false>, cudaFuncAttributeMaxDynamicSharedMemorySize, SMEM_BIG);
    cudaFuncSetAttribute(mma_gemm<128, 64, HE,     false, false, true,  false>, cudaFuncAttributeMaxDynamicSharedMemorySize, SMEM_BIG);
    cudaFuncSetAttribute(mma_gemm<128, 64, D,      true,  true,  false, false>, cudaFuncAttributeMaxDynamicSharedMemorySize, SMEM_BIG);
    cudaFuncSetAttribute(mma_gemm<64,  32, 2 * D,  false, false, false, false>, cudaFuncAttributeMaxDynamicSharedMemorySize, SMEM_SMALL);

    // 1. h = x + pos (transient); LN -> xhat; router input r; zero counts
    posln_kernel<<<NTOK / 8, 256>>>(x, r_ln_g, r_ln_b, p_xhat, p_r, p_counts);
    // 2. router GEMM1 with FUSED logit partials (no rh materialization)
    mma_gemm<128, 64, D, true, false, false, true><<<dim3(H / 128, NTOK / 128), 128, SMEM_LOGIT>>>(
        p_r, r_w1, r_b1, nullptr, nullptr, NTOK, H, r_w2, p_lgp);
    // 3. reduce partials -> softmax -> top2 -> compaction
    router_top2_kernel<<<NTOK / 8, 256>>>(p_lgp, r_b2, temp, p_counts, p_perm, p_te, p_tp, p_tg);
    // 4. gather expert inputs (per-expert LN affine, tf32); bases inline
    gather_kernel<<<dim3(NTOK / 8, E), 256>>>(p_xhat, e_ln_g, e_ln_b, p_counts, p_perm, p_y);
    // 5. expert FFN layer 1
    mma_gemm<128, 64, D, true, true, true, false><<<dim3(HE / 128, NTOK / 128, E), 128, SMEM_BIG>>>(
        p_y, e_w1, e_b1, p_f1, p_counts, 0, HE, nullptr, nullptr);
    // 6. expert FFN layer 2
    mma_gemm<128, 64, HE, false, false, true, false><<<dim3(D / 128, NTOK / 128, E), 128, SMEM_BIG>>>(
        p_f1, e_w2, e_b2, p_f2, p_counts, 0, D, nullptr, nullptr);
    // 7. combine (gates) + combiner LN fused; bases inline
    combine_ln_kernel<<<NTOK / 8, 256>>>(p_f2, p_counts, p_te, p_tp, p_tg, c_ln_g, c_ln_b, p_cln);
    // 8. combiner MLP
    mma_gemm<128, 64, D, true, true, false, false><<<dim3(2 * D / 128, NTOK / 128), 128, SMEM_BIG>>>(
        p_cln, c_w1, c_b1, p_ch, nullptr, NTOK, 2 * D, nullptr, nullptr);
    mma_gemm<64, 32, 2 * D, false, false, false, false><<<dim3(D / 128, NTOK / 64), 128, SMEM_SMALL>>>(
        p_ch, c_w2, c_b2, p_co, nullptr, NTOK, D, nullptr, nullptr);
    // 9. out = LN((x+pos) + co)  (pos recomputed; h never stored)
    lnout_kernel<<<NTOK / 8, 256>>>(x, p_co, o_ln_g, o_ln_b, out);
}

// round 17
// speedup vs baseline: 1.3046x; 1.0156x over previous
#include <cuda_runtime.h>
#include <cstdint>
#include <math.h>

// ---------------- problem constants ----------------
#define NTOK 2048      // B*S
#define D    1024
#define H    4096
#define HE   4096
#define E    8
#define LN_EPS 1e-5f
#define NLB  (H / 128)   // 32 logit partial blocks

// ---------------- scratch (device globals; padded per-expert layout) -------
__device__ float g_xhat [NTOK * D];
__device__ float g_r    [NTOK * D];
__device__ float g_lgp  [NTOK * NLB * E];
__device__ int   g_counts[E];
__device__ int   g_te   [NTOK * 2];
__device__ int   g_tp   [NTOK * 2];
__device__ float g_tg   [NTOK * 2];
__device__ float g_y    [E * NTOK * D];    // [e][slot][D]
__device__ float g_f1   [E * NTOK * HE];   // [e][slot][HE]  (268 MB)
__device__ float g_f2   [E * NTOK * D];    // [e][slot][D]
__device__ float g_cln  [NTOK * D];
__device__ float g_ch   [NTOK * 2 * D];
__device__ float g_co   [NTOK * D];

// ---------------- helpers ----------------
__device__ __forceinline__ float gelu_f(float x) {
    return 0.5f * x * (1.0f + erff(x * 0.7071067811865475f));
}
__device__ __forceinline__ float to_tf32(float x) {
    uint32_t u;
    asm("cvt.rna.tf32.f32 %0, %1;" : "=r"(u) : "f"(x));
    return __uint_as_float(u);
}
__device__ __forceinline__ uint32_t smem_u32(const void* p) {
    uint32_t a;
    asm("{ .reg .u64 t; cvta.to.shared.u64 t, %1; cvt.u32.u64 %0, t; }" : "=r"(a) : "l"(p));
    return a;
}
__device__ __forceinline__ float warp_sum(float v) {
#pragma unroll
    for (int o = 16; o; o >>= 1) v += __shfl_xor_sync(0xffffffffu, v, o);
    return v;
}

// cp.async (baseline PTX, compute_80+)
#define CP_ASYNC_CG(dst, src, srcsz) \
    asm volatile("cp.async.cg.shared.global [%0], [%1], 16, %2;" \
        :: "r"(dst), "l"(src), "r"(srcsz) : "memory")
#define CP_COMMIT() asm volatile("cp.async.commit_group;" ::: "memory")
#define CP_WAIT2()  asm volatile("cp.async.wait_group 2;" ::: "memory")

__device__ __forceinline__ void mma_tf32(float* c, const uint32_t* a, const uint32_t* b) {
    asm volatile(
        "mma.sync.aligned.m16n8k8.row.col.f32.tf32.tf32.f32 "
        "{%0,%1,%2,%3}, {%4,%5,%6,%7}, {%8,%9}, {%0,%1,%2,%3};"
        : "+f"(c[0]), "+f"(c[1]), "+f"(c[2]), "+f"(c[3])
        : "r"(a[0]), "r"(a[1]), "r"(a[2]), "r"(a[3]), "r"(b[0]), "r"(b[1]));
}

// ---------------- elementwise (warp-per-token) ----------------

// h = x + pos (NOT stored); LN -> xhat; r = tf32(xhat*g+b). Also zeroes counts.
__global__ void posln_kernel(const float* __restrict__ x,
                             const float* __restrict__ g, const float* __restrict__ b,
                             float* __restrict__ xhat, float* __restrict__ r,
                             int* __restrict__ counts) {
    if (blockIdx.x == 0 && threadIdx.x < E) counts[threadIdx.x] = 0;
    int wid = threadIdx.x >> 5, lane = threadIdx.x & 31;
    int t = blockIdx.x * 8 + wid;
    int sp = t & 1023;
    const float LOG1E4 = 9.210340371976184f;
    const float4* xr = (const float4*)(x + (size_t)t * D);
    float4 v[8];
    float s = 0.f;
#pragma unroll
    for (int j = 0; j < 8; j++) {
        int idx = j * 32 + lane;
        float4 val = xr[idx];
        int d0 = idx * 4;
        float a0 = (float)sp * expf(-LOG1E4 * (float)d0 * (1.f / (float)D));
        float a1 = (float)sp * expf(-LOG1E4 * (float)(d0 + 2) * (1.f / (float)D));
        float s0, c0, s1, c1;
        sincosf(a0, &s0, &c0);
        sincosf(a1, &s1, &c1);
        val.x += s0; val.y += c0;
        val.z += s1; val.w += c1;
        v[j] = val;
        s += val.x + val.y + val.z + val.w;
    }
    float mean = warp_sum(s) * (1.f / (float)D);
    float q = 0.f;
#pragma unroll
    for (int j = 0; j < 8; j++) {
        float dx = v[j].x - mean, dy = v[j].y - mean, dz = v[j].z - mean, dw = v[j].w - mean;
        q += dx * dx + dy * dy + dz * dz + dw * dw;
    }
    float rstd = rsqrtf(warp_sum(q) * (1.f / (float)D) + LN_EPS);
    float4* xh = (float4*)(xhat + (size_t)t * D);
    float4* rr = (float4*)(r + (size_t)t * D);
    const float4* g4 = (const float4*)g;
    const float4* b4 = (const float4*)b;
#pragma unroll
    for (int j = 0; j < 8; j++) {
        int idx = j * 32 + lane;
        float4 val = v[j];
        float4 xo;
        xo.x = (val.x - mean) * rstd; xo.y = (val.y - mean) * rstd;
        xo.z = (val.z - mean) * rstd; xo.w = (val.w - mean) * rstd;
        xh[idx] = xo;
        float4 gg = g4[idx], bb = b4[idx], ro;
        ro.x = to_tf32(xo.x * gg.x + bb.x); ro.y = to_tf32(xo.y * gg.y + bb.y);
        ro.z = to_tf32(xo.z * gg.z + bb.z); ro.w = to_tf32(xo.w * gg.w + bb.w);
        rr[idx] = ro;
    }
}

// out = LN((x + pos) + co) * g + b  (recomputes pos; identical expressions)
__global__ void lnout_kernel(const float* __restrict__ x, const float* __restrict__ X2,
                             const float* __restrict__ g, const float* __restrict__ b,
                             float* __restrict__ out) {
    int wid = threadIdx.x >> 5, lane = threadIdx.x & 31;
    int t = blockIdx.x * 8 + wid;
    int sp = t & 1023;
    const float LOG1E4 = 9.210340371976184f;
    const float4* xr = (const float4*)(x + (size_t)t * D);
    const float4* x2 = (const float4*)(X2 + (size_t)t * D);
    float4 v[8];
    float s = 0.f;
#pragma unroll
    for (int j = 0; j < 8; j++) {
        int idx = j * 32 + lane;
        float4 a = xr[idx], c = x2[idx];
        int d0 = idx * 4;
        float a0 = (float)sp * expf(-LOG1E4 * (float)d0 * (1.f / (float)D));
        float a1 = (float)sp * expf(-LOG1E4 * (float)(d0 + 2) * (1.f / (float)D));
        float s0, c0, s1, c1;
        sincosf(a0, &s0, &c0);
        sincosf(a1, &s1, &c1);
        a.x += s0 + c.x; a.y += c0 + c.y;
        a.z += s1 + c.z; a.w += c1 + c.w;
        v[j] = a;
        s += a.x + a.y + a.z + a.w;
    }
    float mean = warp_sum(s) * (1.f / (float)D);
    float q = 0.f;
#pragma unroll
    for (int j = 0; j < 8; j++) {
        float dx = v[j].x - mean, dy = v[j].y - mean, dz = v[j].z - mean, dw = v[j].w - mean;
        q += dx * dx + dy * dy + dz * dz + dw * dw;
    }
    float rstd = rsqrtf(warp_sum(q) * (1.f / (float)D) + LN_EPS);
    float4* o4 = (float4*)(out + (size_t)t * D);
    const float4* g4 = (const float4*)g;
    const float4* b4 = (const float4*)b;
#pragma unroll
    for (int j = 0; j < 8; j++) {
        int idx = j * 32 + lane;
        float4 gg = g4[idx], bb = b4[idx], o;
        o.x = (v[j].x - mean) * rstd * gg.x + bb.x;
        o.y = (v[j].y - mean) * rstd * gg.y + bb.y;
        o.z = (v[j].z - mean) * rstd * gg.z + bb.z;
        o.w = (v[j].w - mean) * rstd * gg.w + bb.w;
        o4[idx] = o;
    }
}

// combined = g1*f2[e1][p1] + g2*f2[e2][p2]; cln = tf32(LN(combined)*g+b)
__global__ void combine_ln_kernel(const float* __restrict__ f2,
                                  const int* __restrict__ te, const int* __restrict__ tp,
                                  const float* __restrict__ tg,
                                  const float* __restrict__ g, const float* __restrict__ b,
                                  float* __restrict__ cln) {
    int wid = threadIdx.x >> 5, lane = threadIdx.x & 31;
    int t = blockIdx.x * 8 + wid;
    int e1 = te[2 * t], e2 = te[2 * t + 1];
    int p1 = tp[2 * t], p2 = tp[2 * t + 1];
    float g1 = tg[2 * t], g2 = tg[2 * t + 1];
    const float4* r1 = (const float4*)(f2 + ((size_t)e1 * NTOK + p1) * D);
    const float4* r2 = (const float4*)(f2 + ((size_t)e2 * NTOK + p2) * D);
    float4 v[8];
    float s = 0.f;
#pragma unroll
    for (int j = 0; j < 8; j++) {
        int idx = j * 32 + lane;
        float4 a = r1[idx], c = r2[idx], o;
        o.x = g1 * a.x + g2 * c.x; o.y = g1 * a.y + g2 * c.y;
        o.z = g1 * a.z + g2 * c.z; o.w = g1 * a.w + g2 * c.w;
        v[j] = o;
        s += o.x + o.y + o.z + o.w;
    }
    float mean = warp_sum(s) * (1.f / (float)D);
    float q = 0.f;
#pragma unroll
    for (int j = 0; j < 8; j++) {
        float dx = v[j].x - mean, dy = v[j].y - mean, dz = v[j].z - mean, dw = v[j].w - mean;
        q += dx * dx + dy * dy + dz * dz + dw * dw;
    }
    float rstd = rsqrtf(warp_sum(q) * (1.f / (float)D) + LN_EPS);
    float4* o4 = (float4*)(cln + (size_t)t * D);
    const float4* g4 = (const float4*)g;
    const float4* b4 = (const float4*)b;
#pragma unroll
    for (int j = 0; j < 8; j++) {
        int idx = j * 32 + lane;
        float4 gg = g4[idx], bb = b4[idx], o;
        o.x = to_tf32((v[j].x - mean) * rstd * gg.x + bb.x);
        o.y = to_tf32((v[j].y - mean) * rstd * gg.y + bb.y);
        o.z = to_tf32((v[j].z - mean) * rstd * gg.z + bb.z);
        o.w = to_tf32((v[j].w - mean) * rstd * gg.w + bb.w);
        o4[idx] = o;
    }
}

// router reduce + FUSED gather: warp per token. Reduce lgp partials, softmax,
// top2 (lane 0), broadcast, then the warp copies both affine-transformed xhat
// rows into the padded per-expert y buffer.
__global__ void router_top2_kernel(const float* __restrict__ lgp,
                                   const float* __restrict__ b2, const float* __restrict__ temp,
                                   const float* __restrict__ xhat,
                                   const float* __restrict__ elng, const float* __restrict__ elnb,
                                   int* __restrict__ counts,
                                   int* __restrict__ te, int* __restrict__ tp,
                                   float* __restrict__ tg, float* __restrict__ y) {
    int wid = threadIdx.x >> 5, lane = threadIdx.x & 31;
    int t = blockIdx.x * 8 + wid;
    const float4* src = (const float4*)(lgp + (size_t)t * (NLB * E) + lane * 8);
    float4 va = src[0], vb = src[1];
    float v[E] = {va.x, va.y, va.z, va.w, vb.x, vb.y, vb.z, vb.w};
#pragma unroll
    for (int o = 16; o; o >>= 1)
#pragma unroll
        for (int e = 0; e < E; e++) v[e] += __shfl_xor_sync(0xffffffffu, v[e], o);
    int i1 = 0, i2 = 0, pos1 = 0, pos2 = 0;
    float p1f = 0.f, p2f = 0.f;
    if (lane == 0) {
        float invt = 1.0f / temp[0];
        float p[E];
        float mx = -1e30f;
#pragma unroll
        for (int e = 0; e < E; e++) { p[e] = (v[e] + b2[e]) * invt; mx = fmaxf(mx, p[e]); }
        float se = 0.f;
#pragma unroll
        for (int e = 0; e < E; e++) { p[e] = expf(p[e] - mx); se += p[e]; }
        float inv = 1.0f / se;
#pragma unroll
        for (int e = 0; e < E; e++) p[e] *= inv;
#pragma unroll
        for (int e = 1; e < E; e++) if (p[e] > p[i1]) i1 = e;
        i2 = (i1 == 0) ? 1 : 0;
#pragma unroll
        for (int e = 0; e < E; e++) if (e != i1 && p[e] > p[i2]) i2 = e;
        pos1 = atomicAdd(&counts[i1], 1);
        pos2 = atomicAdd(&counts[i2], 1);
        p1f = p[i1]; p2f = p[i2];
        te[2 * t] = i1; tp[2 * t] = pos1; tg[2 * t] = p1f;
        te[2 * t + 1] = i2; tp[2 * t + 1] = pos2; tg[2 * t + 1] = p2f;
    }
    i1 = __shfl_sync(0xffffffffu, i1, 0);
    i2 = __shfl_sync(0xffffffffu, i2, 0);
    pos1 = __shfl_sync(0xffffffffu, pos1, 0);
    pos2 = __shfl_sync(0xffffffffu, pos2, 0);
    // fused gather: y[e][pos] = tf32(xhat[t]*eg[e]+eb[e]) for both experts
    const float4* xsrc = (const float4*)(xhat + (size_t)t * D);
#pragma unroll
    for (int pass = 0; pass < 2; pass++) {
        int e = pass ? i2 : i1;
        int pos = pass ? pos2 : pos1;
        const float4* g4 = (const float4*)(elng + (size_t)e * D);
        const float4* b4 = (const float4*)(elnb + (size_t)e * D);
        float4* dst = (float4*)(y + ((size_t)e * NTOK + pos) * D);
#pragma unroll
        for (int j = 0; j < 8; j++) {
            int idx = j * 32 + lane;
            float4 s = xsrc[idx], gg = g4[idx], bb = b4[idx], o;
            o.x = to_tf32(s.x * gg.x + bb.x); o.y = to_tf32(s.y * gg.y + bb.y);
            o.z = to_tf32(s.z * gg.z + bb.z); o.w = to_tf32(s.w * gg.w + bb.w);
            dst[idx] = o;
        }
    }
}

// ---------------- tf32 mma.sync GEMM (R16 core; padded grouped layout) ------
// C[M,N] = act(A[M,K] @ B[K,N] + bias[N]); A K-contig, B N-contig.
// BM in {128,64}, BN=128, BK=16, 128 threads (4 warps), FIVE-stage cp.async.
// Issue-first single-stage schedule (safe: issue at kc targets slot of stage
// kc-2; barrier kc-1 separates). Main loop (unconditional issue) + 3-iter tail.
// GROUPED: A/C strided e*NTOK rows (padded layout; no prefix sums).
// LOGITS mode: skip C store, contract post-GELU tile with w2 -> lgp partials.
#define NSTG 5

template <int BM, int WN, int KT, bool DOGELU, bool GROUPED, bool LOGITS>
__global__ void __launch_bounds__(128, (BM == 128) ? 2 : 3)
mma_gemm(const float* __restrict__ Abase, const float* __restrict__ Ball,
         const float* __restrict__ biasall, float* __restrict__ Cbase,
         const int* __restrict__ counts,
         int M_in, int N,
         const float* __restrict__ w2, float* __restrict__ lgp) {
    constexpr int K = KT;
    constexpr int NC = K / 16;
    constexpr int NT = WN / 8;
    constexpr int ACH = BM / 32;
    constexpr int ASTF = BM * 20;
    constexpr int STGF = ASTF + 16 * 136;
    constexpr int STGB = STGF * 4;

    int e = GROUPED ? blockIdx.z : 0;
    int M = GROUPED ? counts[e] : M_in;
    int m0 = blockIdx.y * BM;
    if (m0 >= M) return;
    int n0 = blockIdx.x * 128;
    const float* A = GROUPED ? Abase + (size_t)e * NTOK * K : Abase;
    const float* B = GROUPED ? Ball + (size_t)e * (size_t)K * N : Ball;
    const float* bias = GROUPED ? biasall + (size_t)e * N : biasall;
    float* C = GROUPED ? Cbase + (size_t)e * NTOK * N : Cbase;

    extern __shared__ float smf[];
    uint32_t sbase = smem_u32(smf);
    int tid = threadIdx.x;
    int wid = tid >> 5, lane = tid & 31;
    int gq = lane >> 2, qq = lane & 3;
    int m0w = (BM == 128) ? (wid & 1) * 64 : 0;
    int n0w = (BM == 128) ? (wid >> 1) * 64 : wid * 32;

    int aq = tid & 3, ar = tid >> 2;
    int bq = tid & 31, br = tid >> 5;
    uint32_t adst[ACH], bdst[4];
    const float* asrc[ACH];
    const float* bsrc[4];
    uint32_t asz[ACH];
#pragma unroll
    for (int i = 0; i < ACH; i++) {
        int r = ar + 32 * i;
        adst[i] = (uint32_t)(r * 80 + aq * 16);
        int row = m0 + r;
        asz[i] = (row < M) ? 16u : 0u;
        asrc[i] = A + (size_t)((row < M) ? row : 0) * K + aq * 4;
    }
#pragma unroll
    for (int i = 0; i < 4; i++) {
        int rb = br + 4 * i;
        bdst[i] = (uint32_t)(ASTF * 4 + rb * 544 + bq * 16);
        bsrc[i] = B + (size_t)rb * N + n0 + bq * 4;
    }

    float acc[4][NT][4];
#pragma unroll
    for (int i = 0; i < 4; i++)
#pragma unroll
        for (int j = 0; j < NT; j++)
#pragma unroll
            for (int l = 0; l < 4; l++) acc[i][j][l] = 0.f;

#define ISSUE_STAGE(ST)                                                       \
    do {                                                                      \
        uint32_t sb = sbase + ((ST) % NSTG) * STGB;                           \
        int k0 = (ST) * 16;                                                   \
        _Pragma("unroll")                                                     \
        for (int i = 0; i < ACH; i++) CP_ASYNC_CG(sb + adst[i], asrc[i] + k0, asz[i]); \
        _Pragma("unroll")                                                     \
        for (int i = 0; i < 4; i++) CP_ASYNC_CG(sb + bdst[i], bsrc[i] + (size_t)k0 * N, 16u); \
    } while (0)

#pragma unroll
    for (int pk = 0; pk < 3; pk++) { ISSUE_STAGE(pk); CP_COMMIT(); }
    CP_WAIT2();
    __syncthreads();

    uint32_t a0[4][4], b0[NT][2], a1[4][4], b1[NT][2];

#define LOADFRAG(AF, BF, ASP, BSP, KK)                                        \
    do {                                                                      \
        _Pragma("unroll")                                                     \
        for (int mt = 0; mt < 4; mt++) {                                      \
            int r = m0w + mt * 16 + gq;                                       \
            AF[mt][0] = __float_as_uint((ASP)[r * 20 + (KK) + qq]);           \
            AF[mt][1] = __float_as_uint((ASP)[(r + 8) * 20 + (KK) + qq]);     \
            AF[mt][2] = __float_as_uint((ASP)[r * 20 + (KK) + qq + 4]);       \
            AF[mt][3] = __float_as_uint((ASP)[(r + 8) * 20 + (KK) + qq + 4]); \
        }                                                                     \
        _Pragma("unroll")                                                     \
        for (int nt = 0; nt < NT; nt++) {                                     \
            int c = n0w + nt * 8 + gq;                                        \
            BF[nt][0] = __float_as_uint((BSP)[((KK) + qq) * 136 + c]);        \
            BF[nt][1] = __float_as_uint((BSP)[((KK) + qq + 4) * 136 + c]);    \
        }                                                                     \
    } while (0)

#define MMAALL(AF, BF)                                                        \
    do {                                                                      \
        _Pragma("unroll")                                                     \
        for (int mt = 0; mt < 4; mt++)                                        \
            _Pragma("unroll")                                                 \
            for (int nt = 0; nt < NT; nt++)                                   \
                mma_tf32(acc[mt][nt], AF[mt], BF[nt]);                        \
    } while (0)

#define KBODY(KC)                                                             \
    do {                                                                      \
        CP_COMMIT();                                                          \
        CP_WAIT2();                                                           \
        __syncthreads();                                                      \
        const float* Asc = smf + ((KC) % NSTG) * STGF;                        \
        const float* Bsc = Asc + ASTF;                                        \
        int snn = ((KC) + 1 < NC) ? (((KC) + 1) % NSTG) : ((KC) % NSTG);      \
        const float* Asn = smf + snn * STGF;                                  \
        const float* Bsn = Asn + ASTF;                                        \
        LOADFRAG(a1, b1, Asc, Bsc, 8);                                        \
        MMAALL(a0, b0);                                                       \
        LOADFRAG(a0, b0, Asn, Bsn, 0);                                        \
        MMAALL(a1, b1);                                                       \
    } while (0)

    {
        const float* As0 = smf;
        const float* Bs0 = smf + ASTF;
        LOADFRAG(a0, b0, As0, Bs0, 0);
    }

#pragma unroll 5
    for (int kc = 0; kc < NC - 3; kc++) {
        ISSUE_STAGE(kc + 3);
        KBODY(kc);
    }
#pragma unroll
    for (int kc = NC - 3; kc < NC; kc++) {
        KBODY(kc);
    }
#undef KBODY
#undef LOADFRAG
#undef MMAALL
#undef ISSUE_STAGE

    // ---------------- epilogue ----------------
    float* lgs = smf + NSTG * STGF;
    if (LOGITS) {
#pragma unroll
        for (int i = 0; i < 8; i++) lgs[i * 128 + tid] = 0.f;
        __syncthreads();
    }

#pragma unroll
    for (int mt = 0; mt < 4; mt++) {
        int row0 = m0 + m0w + mt * 16 + gq;
        int row1 = row0 + 8;
        float lg0[E], lg1[E];
        if (LOGITS) {
#pragma unroll
            for (int ee = 0; ee < E; ee++) { lg0[ee] = 0.f; lg1[ee] = 0.f; }
        }
#pragma unroll
        for (int nt = 0; nt < NT; nt++) {
            int col = n0 + n0w + nt * 8 + 2 * qq;
            float bb0 = bias[col], bb1 = bias[col + 1];
            float v0 = acc[mt][nt][0] + bb0;
            float v1 = acc[mt][nt][1] + bb1;
            float v2 = acc[mt][nt][2] + bb0;
            float v3 = acc[mt][nt][3] + bb1;
            if (DOGELU) { v0 = gelu_f(v0); v1 = gelu_f(v1); v2 = gelu_f(v2); v3 = gelu_f(v3); }
            if (LOGITS) {
                const float4* wr0 = (const float4*)(w2 + (size_t)col * E);
                float4 wa = wr0[0], wb = wr0[1];
                const float4* wr1 = (const float4*)(w2 + (size_t)(col + 1) * E);
                float4 wc = wr1[0], wd = wr1[1];
                lg0[0] += v0 * wa.x + v1 * wc.x; lg0[1] += v0 * wa.y + v1 * wc.y;
                lg0[2] += v0 * wa.z + v1 * wc.z; lg0[3] += v0 * wa.w + v1 * wc.w;
                lg0[4] += v0 * wb.x + v1 * wd.x; lg0[5] += v0 * wb.y + v1 * wd.y;
                lg0[6] += v0 * wb.z + v1 * wd.z; lg0[7] += v0 * wb.w + v1 * wd.w;
                lg1[0] += v2 * wa.x + v3 * wc.x; lg1[1] += v2 * wa.y + v3 * wc.y;
                lg1[2] += v2 * wa.z + v3 * wc.z; lg1[3] += v2 * wa.w + v3 * wc.w;
                lg1[4] += v2 * wb.x + v3 * wd.x; lg1[5] += v2 * wb.y + v3 * wd.y;
                lg1[6] += v2 * wb.z + v3 * wd.z; lg1[7] += v2 * wb.w + v3 * wd.w;
            } else {
                if (row0 < M) *(float2*)(C + (size_t)row0 * N + col) = make_float2(v0, v1);
                if (row1 < M) *(float2*)(C + (size_t)row1 * N + col) = make_float2(v2, v3);
            }
        }
        if (LOGITS) {
#pragma unroll
            for (int off = 1; off <= 2; off <<= 1)
#pragma unroll
                for (int ee = 0; ee < E; ee++) {
                    lg0[ee] += __shfl_xor_sync(0xffffffffu, lg0[ee], off);
                    lg1[ee] += __shfl_xor_sync(0xffffffffu, lg1[ee], off);
                }
            if (qq == 0) {
                int r0 = m0w + mt * 16 + gq;
                int r1 = r0 + 8;
#pragma unroll
                for (int ee = 0; ee < E; ee++) {
                    atomicAdd(&lgs[r0 * E + ee], lg0[ee]);   // exactly 2 adds/cell
                    atomicAdd(&lgs[r1 * E + ee], lg1[ee]);   // -> deterministic
                }
            }
        }
    }

    if (LOGITS) {
        __syncthreads();
        int row = tid;
        float4* dst = (float4*)(lgp + ((size_t)(m0 + row) * NLB + blockIdx.x) * E);
        const float4* src = (const float4*)&lgs[row * E];
        dst[0] = src[0];
        dst[1] = src[1];
    }
}

#define SMEM_BIG   (NSTG * (128 * 20 + 16 * 136) * 4)
#define SMEM_LOGIT (SMEM_BIG + 128 * E * 4)
#define SMEM_SMALL (NSTG * (64 * 20 + 16 * 136) * 4)

// ---------------- launch ----------------
extern "C" void kernel_launch(void* const* d_in, const int* in_sizes, int n_in,
                              void* d_out, int out_size) {
    const float* x      = (const float*)d_in[0];
    const float* r_ln_g = (const float*)d_in[1];
    const float* r_ln_b = (const float*)d_in[2];
    const float* r_w1   = (const float*)d_in[3];
    const float* r_b1   = (const float*)d_in[4];
    const float* r_w2   = (const float*)d_in[5];
    const float* r_b2   = (const float*)d_in[6];
    const float* temp   = (const float*)d_in[7];
    const float* e_ln_g = (const float*)d_in[8];
    const float* e_ln_b = (const float*)d_in[9];
    const float* e_w1   = (const float*)d_in[10];
    const float* e_b1   = (const float*)d_in[11];
    const float* e_w2   = (const float*)d_in[12];
    const float* e_b2   = (const float*)d_in[13];
    const float* c_ln_g = (const float*)d_in[14];
    const float* c_ln_b = (const float*)d_in[15];
    const float* c_w1   = (const float*)d_in[16];
    const float* c_b1   = (const float*)d_in[17];
    const float* c_w2   = (const float*)d_in[18];
    const float* c_b2   = (const float*)d_in[19];
    const float* o_ln_g = (const float*)d_in[20];
    const float* o_ln_b = (const float*)d_in[21];
    float* out = (float*)d_out;

    float *p_xhat, *p_r, *p_lgp, *p_tg, *p_y, *p_f1, *p_f2, *p_cln, *p_ch, *p_co;
    int *p_counts, *p_te, *p_tp;
    cudaGetSymbolAddress((void**)&p_xhat, g_xhat);
    cudaGetSymbolAddress((void**)&p_r, g_r);
    cudaGetSymbolAddress((void**)&p_lgp, g_lgp);
    cudaGetSymbolAddress((void**)&p_counts, g_counts);
    cudaGetSymbolAddress((void**)&p_te, g_te);
    cudaGetSymbolAddress((void**)&p_tp, g_tp);
    cudaGetSymbolAddress((void**)&p_tg, g_tg);
    cudaGetSymbolAddress((void**)&p_y, g_y);
    cudaGetSymbolAddress((void**)&p_f1, g_f1);
    cudaGetSymbolAddress((void**)&p_f2, g_f2);
    cudaGetSymbolAddress((void**)&p_cln, g_cln);
    cudaGetSymbolAddress((void**)&p_ch, g_ch);
    cudaGetSymbolAddress((void**)&p_co, g_co);

    cudaFuncSetAttribute(mma_gemm<128, 64, D,      true,  false, true >, cudaFuncAttributeMaxDynamicSharedMemorySize, SMEM_LOGIT);
    cudaFuncSetAttribute(mma_gemm<128, 64, D,      true,  true,  false>, cudaFuncAttributeMaxDynamicSharedMemorySize, SMEM_BIG);
    cudaFuncSetAttribute(mma_gemm<128, 64, HE,     false, true,  false>, cudaFuncAttributeMaxDynamicSharedMemorySize, SMEM_BIG);
    cudaFuncSetAttribute(mma_gemm<128, 64, D,      true,  false, false>, cudaFuncAttributeMaxDynamicSharedMemorySize, SMEM_BIG);
    cudaFuncSetAttribute(mma_gemm<64,  32, 2 * D,  false, false, false>, cudaFuncAttributeMaxDynamicSharedMemorySize, SMEM_SMALL);

    // 1. h = x + pos (transient); LN -> xhat; router input r; zero counts
    posln_kernel<<<NTOK / 8, 256>>>(x, r_ln_g, r_ln_b, p_xhat, p_r, p_counts);
    // 2. router GEMM1 with FUSED logit partials (no rh materialization)
    mma_gemm<128, 64, D, true, false, true><<<dim3(H / 128, NTOK / 128), 128, SMEM_LOGIT>>>(
        p_r, r_w1, r_b1, nullptr, nullptr, NTOK, H, r_w2, p_lgp);
    // 3. reduce partials -> softmax -> top2 -> FUSED gather into padded y
    router_top2_kernel<<<NTOK / 8, 256>>>(p_lgp, r_b2, temp, p_xhat, e_ln_g, e_ln_b,
                                          p_counts, p_te, p_tp, p_tg, p_y);
    // 4. expert FFN layer 1 (padded layout; f1 unrounded - HW truncates to tf32)
    mma_gemm<128, 64, D, true, true, false><<<dim3(HE / 128, NTOK / 128, E), 128, SMEM_BIG>>>(
        p_y, e_w1, e_b1, p_f1, p_counts, 0, HE, nullptr, nullptr);
    // 5. expert FFN layer 2
    mma_gemm<128, 64, HE, false, true, false><<<dim3(D / 128, NTOK / 128, E), 128, SMEM_BIG>>>(
        p_f1, e_w2, e_b2, p_f2, p_counts, 0, D, nullptr, nullptr);
    // 6. combine (gates) + combiner LN fused (padded indexing)
    combine_ln_kernel<<<NTOK / 8, 256>>>(p_f2, p_te, p_tp, p_tg, c_ln_g, c_ln_b, p_cln);
    // 7. combiner MLP (ch unrounded - HW truncates)
    mma_gemm<128, 64, D, true, false, false><<<dim3(2 * D / 128, NTOK / 128), 128, SMEM_BIG>>>(
        p_cln, c_w1, c_b1, p_ch, nullptr, NTOK, 2 * D, nullptr, nullptr);
    mma_gemm<64, 32, 2 * D, false, false, false><<<dim3(D / 128, NTOK / 64), 128, SMEM_SMALL>>>(
        p_ch, c_w2, c_b2, p_co, nullptr, NTOK, D, nullptr, nullptr);
    // 8. out = LN((x+pos) + co)
    lnout_kernel<<<NTOK / 8, 256>>>(x, p_co, o_ln_g, o_ln_b, out);
}